// round 11
// baseline (speedup 1.0000x reference)
#include <cuda_runtime.h>
#include <cuda_fp16.h>
#include <cstdint>

// Problem constants
#define DIMX 768
#define HQ   8
#define HKV  2
#define HD   64
#define SEQ  4096
#define NREP (HQ / HKV)   // 4
#define RSPLIT 2          // rowsum key split

// Scratch (allocation-free rule: __device__ globals)
__device__ float  g_Q[SEQ * HQ * HD];           // fp32
__device__ float  g_K[SEQ * HKV * HD];          // fp32
__device__ float  g_V[SEQ * HKV * HD];          // fp32
__device__ __half g_Kh[SEQ * HKV * HD];         // half, pair-interleaved d
__device__ __half g_Vt[HKV * HD * SEQ];         // [2][64][4096] half, transposed, pair-interleaved s
__device__ float  g_C[SEQ * HQ * HD];           // context
__device__ float  g_rspart[RSPLIT * HQ * SEQ];  // rowsum partials

// ===========================================================================
// helpers
// ===========================================================================
__device__ __forceinline__ float f2tf32(float x) {
    uint32_t u;
    asm("cvt.rna.tf32.f32 %0, %1;" : "=r"(u) : "f"(x));
    return __uint_as_float(u);
}
__device__ __forceinline__ float4 tf32x4(float4 v) {
    float4 w;
    w.x = f2tf32(v.x); w.y = f2tf32(v.y); w.z = f2tf32(v.z); w.w = f2tf32(v.w);
    return w;
}
__device__ __forceinline__ void mma_tf32(float* c, const uint32_t* a, const uint32_t* b) {
    asm volatile(
        "mma.sync.aligned.m16n8k8.row.col.f32.tf32.tf32.f32 "
        "{%0,%1,%2,%3}, {%4,%5,%6,%7}, {%8,%9}, {%0,%1,%2,%3};"
        : "+f"(c[0]), "+f"(c[1]), "+f"(c[2]), "+f"(c[3])
        : "r"(a[0]), "r"(a[1]), "r"(a[2]), "r"(a[3]), "r"(b[0]), "r"(b[1]));
}
__device__ __forceinline__ void mma_f16(float* c, const uint32_t* a, uint32_t b0, uint32_t b1) {
    asm volatile(
        "mma.sync.aligned.m16n8k16.row.col.f32.f16.f16.f32 "
        "{%0,%1,%2,%3}, {%4,%5,%6,%7}, {%8,%9}, {%0,%1,%2,%3};"
        : "+f"(c[0]), "+f"(c[1]), "+f"(c[2]), "+f"(c[3])
        : "r"(a[0]), "r"(a[1]), "r"(a[2]), "r"(a[3]), "r"(b0), "r"(b1));
}
__device__ __forceinline__ uint32_t pack2(float a, float b) {
    __half2 h = __floats2half2_rn(a, b);
    return *reinterpret_cast<uint32_t*>(&h);
}
__device__ __forceinline__ float ex2(float x) {
    float y;
    asm("ex2.approx.f32 %0, %1;" : "=f"(y) : "f"(x));
    return y;
}
__device__ __forceinline__ void stg_cs_v2(float* p, float a, float b) {
    asm volatile("st.global.cs.v2.f32 [%0], {%1, %2};"
                 :: "l"(p), "f"(a), "f"(b) : "memory");
}
__device__ __forceinline__ uint32_t fbits(float x) { return __float_as_uint(x); }

// scale baked into Q fragments: 1/sqrt(64) * log2(e)
#define QSCALE 0.1803368801111204f

#define APAD 68
#define BPAD 72
#define HPAD 80   // half tile stride (halves); conflict-free for LDS.64 frags

// ===========================================================================
// Prep: fp32 K -> half Kh, pair-interleaved d within each 16-group.
// ===========================================================================
__global__ void k2h_kernel(const float* __restrict__ K, __half* __restrict__ Kh)
{
    int i = blockIdx.x * 256 + threadIdx.x;   // uint2 index
    int u = i & 3;
    int chunk = i >> 2;
    const float* src = K + (size_t)chunk * 16 + 2 * u;
    float2 lo = *(const float2*)src;
    float2 hi = *(const float2*)(src + 8);
    uint2 o;
    o.x = pack2(lo.x, lo.y);
    o.y = pack2(hi.x, hi.y);
    *(uint2*)((char*)Kh + (size_t)i * 8) = o;
}

// ===========================================================================
// Prep: fp32 V -> half Vt [kh][d][s_perm], s pair-interleaved per 16-group.
// ===========================================================================
__device__ __forceinline__ int perm16(int s) {
    int q = s & 15;
    int p = (q < 8) ? ((q >> 1) * 4 + (q & 1))
                    : (((q - 8) >> 1) * 4 + 2 + (q & 1));
    return (s & ~15) | p;
}

__global__ void vt_kernel(const float* __restrict__ V, __half* __restrict__ Vt)
{
    __shared__ float tile[32][33];
    const int kh = blockIdx.z;
    const int s0 = blockIdx.x * 32;
    const int d0 = blockIdx.y * 32;
    const int tx = threadIdx.x, ty = threadIdx.y;
#pragma unroll
    for (int i = 0; i < 32; i += 8)
        tile[ty + i][tx] = V[(size_t)(s0 + ty + i) * (HKV * HD) + kh * HD + d0 + tx];
    __syncthreads();
#pragma unroll
    for (int i = 0; i < 32; i += 8)
        Vt[(size_t)kh * HD * SEQ + (size_t)(d0 + ty + i) * SEQ + s0 + perm16(tx)] =
            __float2half_rn(tile[tx][ty + i]);
}

// ===========================================================================
// Q fragment loader (16 rows, scaled). Natural k-slot order.
// ===========================================================================
__device__ __forceinline__ void load_qfrag(
    uint32_t qf[4][4], const float* __restrict__ Q,
    int row0, int h, int g, int t4)
{
    const float* q0 = Q + (size_t)(row0 + g) * (HQ * HD) + h * HD;
    const float* q1 = q0 + (size_t)8 * (HQ * HD);
#pragma unroll
    for (int ks = 0; ks < 4; ks++) {
        int c = ks * 16 + t4 * 2;
        qf[ks][0] = pack2(q0[c] * QSCALE, q0[c + 1] * QSCALE);
        qf[ks][1] = pack2(q1[c] * QSCALE, q1[c + 1] * QSCALE);
        qf[ks][2] = pack2(q0[c + 8] * QSCALE, q0[c + 9] * QSCALE);
        qf[ks][3] = pack2(q1[c + 8] * QSCALE, q1[c + 9] * QSCALE);
    }
}

// B-fragment: one LDS.64 from pair-interleaved storage
__device__ __forceinline__ uint2 bfrag(const __half* base, int n, int ks, int t4) {
    return *(const uint2*)(base + n * HPAD + ks * 16 + t4 * 4);
}

// ===========================================================================
// Pass 1: partial rowsums. 128 thr, 4 warps x 32 rows = 128-row tile.
// grid (SEQ/128, HQ, RSPLIT). N=128 key tiles.
// ===========================================================================
__global__ __launch_bounds__(128) void rowsum_kernel(
    const float* __restrict__ Q, const __half* __restrict__ Kh,
    float* __restrict__ rspart)
{
    __shared__ __half Ks[128 * HPAD];

    const int t = threadIdx.x, lane = t & 31, wid = t >> 5;
    const int g = lane >> 2, t4 = lane & 3;
    const int m0 = blockIdx.x * 128, h = blockIdx.y, sp = blockIdx.z;
    const int kh = h / NREP;

    uint32_t qfA[4][4], qfB[4][4];
    load_qfrag(qfA, Q, m0 + wid * 32, h, g, t4);
    load_qfrag(qfB, Q, m0 + wid * 32 + 16, h, g, t4);

    float rs[4] = {0.f, 0.f, 0.f, 0.f};
    const int it0 = sp * (SEQ / 128 / RSPLIT);
    const int it1 = it0 + (SEQ / 128 / RSPLIT);

    for (int it = it0; it < it1; it++) {
        const int n0 = it * 128;
        __syncthreads();
#pragma unroll
        for (int i = 0; i < 8; i++) {
            int e = t + i * 128;
            int r = e >> 3, seg = e & 7;
            *(uint4*)&Ks[r * HPAD + seg * 8] =
                *(const uint4*)(Kh + (size_t)(n0 + r) * (HKV * HD) + kh * HD + seg * 8);
        }
        __syncthreads();

#pragma unroll
        for (int j = 0; j < 16; j++) {
            float sA[4] = {0.f, 0.f, 0.f, 0.f};
            float sB[4] = {0.f, 0.f, 0.f, 0.f};
#pragma unroll
            for (int ks = 0; ks < 4; ks++) {
                uint2 b = bfrag(Ks, j * 8 + g, ks, t4);
                mma_f16(sA, qfA[ks], b.x, b.y);
                mma_f16(sB, qfB[ks], b.x, b.y);
            }
            rs[0] += ex2(sA[0]) + ex2(sA[1]);
            rs[1] += ex2(sA[2]) + ex2(sA[3]);
            rs[2] += ex2(sB[0]) + ex2(sB[1]);
            rs[3] += ex2(sB[2]) + ex2(sB[3]);
        }
    }

#pragma unroll
    for (int i = 0; i < 4; i++) {
        rs[i] += __shfl_xor_sync(0xffffffffu, rs[i], 1);
        rs[i] += __shfl_xor_sync(0xffffffffu, rs[i], 2);
    }
    if (t4 == 0) {
        float* dst = rspart + (size_t)sp * HQ * SEQ + (size_t)h * SEQ + m0 + wid * 32;
        dst[g]      = rs[0];
        dst[g + 8]  = rs[1];
        dst[g + 16] = rs[2];
        dst[g + 24] = rs[3];
    }
}

// ===========================================================================
// Pass 2 (round-9 shape): fused scores + softmax write (.cs) + PV.
// 128 thr, 4 warps x 16 rows. grid (SEQ/64, HQ).
// ===========================================================================
__global__ __launch_bounds__(128) void fused_att_kernel(
    const float* __restrict__ Q, const __half* __restrict__ Kh,
    const __half* __restrict__ Vt, const float* __restrict__ rspart,
    float* __restrict__ att, float* __restrict__ Ctx)
{
    __shared__ __half Ks[64 * HPAD];
    __shared__ __half Vs[64 * HPAD];
    __shared__ float sinv[64];

    const int t = threadIdx.x, lane = t & 31, wid = t >> 5;
    const int g = lane >> 2, t4 = lane & 3;
    const int m0 = blockIdx.x * 64, h = blockIdx.y;
    const int kh = h / NREP;

    if (t < 64) {
        const float* rp = rspart + (size_t)h * SEQ + m0 + t;
        float s = rp[0];
#pragma unroll
        for (int i = 1; i < RSPLIT; i++) s += rp[(size_t)i * HQ * SEQ];
        sinv[t] = 1.0f / s;
    }

    uint32_t qf[4][4];
    load_qfrag(qf, Q, m0 + wid * 16, h, g, t4);
    __syncthreads();

    const int rl = wid * 16 + g;
    const float inv_lo = sinv[rl];
    const float inv_hi = sinv[rl + 8];
    const __half* vth = Vt + (size_t)kh * HD * SEQ;

    float ctx[8][4];
#pragma unroll
    for (int j = 0; j < 8; j++)
#pragma unroll
        for (int c = 0; c < 4; c++) ctx[j][c] = 0.f;

    float* atth = att + (size_t)h * SEQ * SEQ;

    for (int it = 0; it < SEQ / 64; it++) {
        const int k0 = it * 64;
        __syncthreads();
#pragma unroll
        for (int i = 0; i < 4; i++) {
            int e = t + i * 128;
            int r = e >> 3, seg = e & 7;
            *(uint4*)&Ks[r * HPAD + seg * 8] =
                *(const uint4*)(Kh + (size_t)(k0 + r) * (HKV * HD) + kh * HD + seg * 8);
            *(uint4*)&Vs[r * HPAD + seg * 8] =
                *(const uint4*)(vth + (size_t)r * SEQ + k0 + seg * 8);
        }
        __syncthreads();

        // scores: 16 rows x 64 keys
        float sacc[8][4];
#pragma unroll
        for (int j = 0; j < 8; j++)
#pragma unroll
            for (int c = 0; c < 4; c++) sacc[j][c] = 0.f;

#pragma unroll
        for (int ks = 0; ks < 4; ks++) {
#pragma unroll
            for (int j = 0; j < 8; j++) {
                uint2 b = bfrag(Ks, j * 8 + g, ks, t4);
                mma_f16(sacc[j], qf[ks], b.x, b.y);
            }
        }

        // epilogue: p = ex2(sacc)*inv -> att (.cs), pack to fp16 A-frags
        const size_t rowbase = (size_t)(m0 + rl) * SEQ + k0;
        uint32_t pk[8][2];
#pragma unroll
        for (int j = 0; j < 8; j++) {
            float p0 = ex2(sacc[j][0]) * inv_lo;
            float p1 = ex2(sacc[j][1]) * inv_lo;
            float p2 = ex2(sacc[j][2]) * inv_hi;
            float p3 = ex2(sacc[j][3]) * inv_hi;
            int cj = j * 8 + t4 * 2;
            stg_cs_v2(atth + rowbase + cj, p0, p1);
            stg_cs_v2(atth + rowbase + 8 * SEQ + cj, p2, p3);
            pk[j][0] = pack2(p0, p1);
            pk[j][1] = pack2(p2, p3);
        }

        // PV: A-frags = packed score C-frags (natural key slots)
#pragma unroll
        for (int kc = 0; kc < 4; kc++) {
            uint32_t A[4] = { pk[2 * kc][0], pk[2 * kc][1],
                              pk[2 * kc + 1][0], pk[2 * kc + 1][1] };
#pragma unroll
            for (int jj = 0; jj < 8; jj++) {
                uint2 b = bfrag(Vs, jj * 8 + g, kc, t4);
                mma_f16(ctx[jj], A, b.x, b.y);
            }
        }
    }

    // store context
#pragma unroll
    for (int jj = 0; jj < 8; jj++) {
        int col = h * HD + jj * 8 + t4 * 2;
        *(float2*)(Ctx + (size_t)(m0 + rl) * (HQ * HD) + col) =
            make_float2(ctx[jj][0], ctx[jj][1]);
        *(float2*)(Ctx + (size_t)(m0 + rl + 8) * (HQ * HD) + col) =
            make_float2(ctx[jj][2], ctx[jj][3]);
    }
}

// ===========================================================================
// Projections (tf32 mma), BM=64 x BN=64, BK=64. 256 thr, warps 4(m) x 2(n).
// ===========================================================================
#define PJ_AS 0
#define PJ_BS (64 * APAD)
#define PJ_SMEM_BYTES ((PJ_BS + 64 * BPAD) * 4)

__device__ __forceinline__ void proj_body(
    const float* __restrict__ A, int lda,
    const float* __restrict__ B, int ldb,
    const float* __restrict__ bias,
    float* __restrict__ C, int ldc, int Kdim, int m0, int n0)
{
    extern __shared__ float sm[];
    float* As = sm + PJ_AS;
    float* Bs = sm + PJ_BS;

    const int t = threadIdx.x, lane = t & 31, wid = t >> 5;
    const int wm = wid >> 1, wn = wid & 1;   // 4(m) x 2(n)
    const int g = lane >> 2, t4 = lane & 3;

    float acc[4][4];
#pragma unroll
    for (int j = 0; j < 4; j++)
#pragma unroll
        for (int c = 0; c < 4; c++) acc[j][c] = 0.f;

    for (int k0 = 0; k0 < Kdim; k0 += 64) {
        float4 av[4], bv[4];
#pragma unroll
        for (int i = 0; i < 4; i++) {
            int e = t + i * 256;
            int r = e >> 4, q = e & 15;
            av[i] = tf32x4(*(const float4*)(A + (size_t)(m0 + r) * lda + k0 + q * 4));
            bv[i] = tf32x4(*(const float4*)(B + (size_t)(k0 + r) * ldb + n0 + q * 4));
        }
        __syncthreads();
#pragma unroll
        for (int i = 0; i < 4; i++) {
            int e = t + i * 256;
            int r = e >> 4, q = e & 15;
            *(float4*)&As[r * APAD + q * 4] = av[i];
            *(float4*)&Bs[r * BPAD + q * 4] = bv[i];
        }
        __syncthreads();

#pragma unroll
        for (int ks = 0; ks < 8; ks++) {
            const int kk = ks * 8;
            const int r = wm * 16 + g;
            uint32_t Af[4] = {
                fbits(As[r * APAD + kk + t4]),
                fbits(As[(r + 8) * APAD + kk + t4]),
                fbits(As[r * APAD + kk + t4 + 4]),
                fbits(As[(r + 8) * APAD + kk + t4 + 4]) };
#pragma unroll
            for (int j = 0; j < 4; j++) {
                int n = wn * 32 + j * 8 + g;
                uint32_t Bf[2] = {
                    fbits(Bs[(kk + t4) * BPAD + n]),
                    fbits(Bs[(kk + t4 + 4) * BPAD + n]) };
                mma_tf32(acc[j], Af, Bf);
            }
        }
        __syncthreads();
    }

    const int r0 = m0 + wm * 16 + g;
#pragma unroll
    for (int j = 0; j < 4; j++) {
        int col = n0 + wn * 32 + j * 8 + t4 * 2;
        float b0 = bias[col], b1 = bias[col + 1];
        *(float2*)(C + (size_t)r0 * ldc + col) =
            make_float2(acc[j][0] + b0, acc[j][1] + b1);
        *(float2*)(C + (size_t)(r0 + 8) * ldc + col) =
            make_float2(acc[j][2] + b0, acc[j][3] + b1);
    }
}

__global__ __launch_bounds__(256) void qkv_proj_kernel(
    const float* __restrict__ x,
    const float* __restrict__ Wq, const float* __restrict__ bq,
    const float* __restrict__ Wk, const float* __restrict__ bk,
    const float* __restrict__ Wv, const float* __restrict__ bv,
    float* __restrict__ Qo, float* __restrict__ Ko, float* __restrict__ Vo)
{
    const int seg = blockIdx.x;
    const int m0 = blockIdx.y * 64;
    const float *W, *bias;
    float* C;
    int ld, n0;
    if (seg < 8)       { W = Wq; bias = bq; C = Qo; ld = HQ * HD;  n0 = seg * 64; }
    else if (seg < 10) { W = Wk; bias = bk; C = Ko; ld = HKV * HD; n0 = (seg - 8) * 64; }
    else               { W = Wv; bias = bv; C = Vo; ld = HKV * HD; n0 = (seg - 10) * 64; }
    proj_body(x, DIMX, W, ld, bias, C, ld, DIMX, m0, n0);
}

__global__ __launch_bounds__(256) void out_proj_kernel(
    const float* __restrict__ Ctx, const float* __restrict__ Wo,
    const float* __restrict__ bo, float* __restrict__ out)
{
    proj_body(Ctx, HQ * HD, Wo, DIMX, bo, out, DIMX, HQ * HD,
              blockIdx.y * 64, blockIdx.x * 64);
}

// ===========================================================================
extern "C" void kernel_launch(void* const* d_in, const int* in_sizes, int n_in,
                              void* d_out, int out_size)
{
    const float* x  = (const float*)d_in[0];
    const float* Wq = (const float*)d_in[1];
    const float* bq = (const float*)d_in[2];
    const float* Wk = (const float*)d_in[3];
    const float* bk = (const float*)d_in[4];
    const float* Wv = (const float*)d_in[5];
    const float* bv = (const float*)d_in[6];
    const float* Wo = (const float*)d_in[7];
    const float* bo = (const float*)d_in[8];

    float* out = (float*)d_out;                 // [4096, 768]
    float* att = out + (size_t)SEQ * DIMX;      // [8, 4096, 4096]

    void* p;
    cudaGetSymbolAddress(&p, g_Q);      float*  Qp  = (float*)p;
    cudaGetSymbolAddress(&p, g_K);      float*  Kp  = (float*)p;
    cudaGetSymbolAddress(&p, g_V);      float*  Vp  = (float*)p;
    cudaGetSymbolAddress(&p, g_Kh);     __half* Khp = (__half*)p;
    cudaGetSymbolAddress(&p, g_Vt);     __half* Vtp = (__half*)p;
    cudaGetSymbolAddress(&p, g_C);      float*  Cp  = (float*)p;
    cudaGetSymbolAddress(&p, g_rspart); float*  Rpp = (float*)p;

    cudaFuncSetAttribute(qkv_proj_kernel,
        cudaFuncAttributeMaxDynamicSharedMemorySize, PJ_SMEM_BYTES);
    cudaFuncSetAttribute(out_proj_kernel,
        cudaFuncAttributeMaxDynamicSharedMemorySize, PJ_SMEM_BYTES);

    // QKV projections (BM=64, grid 12 x 64 = 768 blocks)
    qkv_proj_kernel<<<dim3(12, SEQ / 64), 256, PJ_SMEM_BYTES>>>(
        x, Wq, bq, Wk, bk, Wv, bv, Qp, Kp, Vp);

    // preps (pair-interleaved layouts)
    k2h_kernel<<<(SEQ * HKV * HD) / 4 / 256, 256>>>(Kp, Khp);
    vt_kernel<<<dim3(SEQ / 32, HD / 32, HKV), dim3(32, 8)>>>(Vp, Vtp);

    // Pass 1: partial rowsums (4 warps x 32 rows, 128 thr)
    rowsum_kernel<<<dim3(SEQ / 128, HQ, RSPLIT), 128>>>(Qp, Khp, Rpp);

    // Pass 2: fused scores + softmax write + PV (round-9 shape)
    fused_att_kernel<<<dim3(SEQ / 64, HQ), 128>>>(Qp, Khp, Vtp, Rpp, att, Cp);

    // out = ctx @ Wo + bo (BM=64, grid 12 x 64 = 768 blocks)
    out_proj_kernel<<<dim3(DIMX / 64, SEQ / 64), 256, PJ_SMEM_BYTES>>>(
        Cp, Wo, bo, out);
}

// round 12
// speedup vs baseline: 1.0971x; 1.0971x over previous
#include <cuda_runtime.h>
#include <cuda_fp16.h>
#include <cstdint>

// Problem constants
#define DIMX 768
#define HQ   8
#define HKV  2
#define HD   64
#define SEQ  4096
#define NREP (HQ / HKV)   // 4
#define RSPLIT 2          // rowsum key split

// Scratch (allocation-free rule: __device__ globals)
__device__ float  g_Q[SEQ * HQ * HD];           // fp32
__device__ float  g_K[SEQ * HKV * HD];          // fp32
__device__ float  g_V[SEQ * HKV * HD];          // fp32
__device__ __half g_Kh[SEQ * HKV * HD];         // half, pair-interleaved d
__device__ __half g_Vt[HKV * HD * SEQ];         // [2][64][4096] half, transposed, pair-interleaved s
__device__ float  g_C[SEQ * HQ * HD];           // context
__device__ float  g_rspart[RSPLIT * HQ * SEQ];  // rowsum partials

// ===========================================================================
// helpers
// ===========================================================================
__device__ __forceinline__ float f2tf32(float x) {
    uint32_t u;
    asm("cvt.rna.tf32.f32 %0, %1;" : "=r"(u) : "f"(x));
    return __uint_as_float(u);
}
__device__ __forceinline__ float4 tf32x4(float4 v) {
    float4 w;
    w.x = f2tf32(v.x); w.y = f2tf32(v.y); w.z = f2tf32(v.z); w.w = f2tf32(v.w);
    return w;
}
__device__ __forceinline__ void mma_tf32(float* c, const uint32_t* a, const uint32_t* b) {
    asm volatile(
        "mma.sync.aligned.m16n8k8.row.col.f32.tf32.tf32.f32 "
        "{%0,%1,%2,%3}, {%4,%5,%6,%7}, {%8,%9}, {%0,%1,%2,%3};"
        : "+f"(c[0]), "+f"(c[1]), "+f"(c[2]), "+f"(c[3])
        : "r"(a[0]), "r"(a[1]), "r"(a[2]), "r"(a[3]), "r"(b[0]), "r"(b[1]));
}
__device__ __forceinline__ void mma_f16(float* c, const uint32_t* a, uint32_t b0, uint32_t b1) {
    asm volatile(
        "mma.sync.aligned.m16n8k16.row.col.f32.f16.f16.f32 "
        "{%0,%1,%2,%3}, {%4,%5,%6,%7}, {%8,%9}, {%0,%1,%2,%3};"
        : "+f"(c[0]), "+f"(c[1]), "+f"(c[2]), "+f"(c[3])
        : "r"(a[0]), "r"(a[1]), "r"(a[2]), "r"(a[3]), "r"(b0), "r"(b1));
}
__device__ __forceinline__ uint32_t pack2(float a, float b) {
    __half2 h = __floats2half2_rn(a, b);
    return *reinterpret_cast<uint32_t*>(&h);
}
__device__ __forceinline__ float ex2(float x) {
    float y;
    asm("ex2.approx.f32 %0, %1;" : "=f"(y) : "f"(x));
    return y;
}
// two exponentials in one MUFU op (fp16x2); returns fp32 pair
__device__ __forceinline__ float2 ex2h2(float a, float b) {
    uint32_t in = pack2(a, b);
    uint32_t out;
    asm("ex2.approx.f16x2 %0, %1;" : "=r"(out) : "r"(in));
    __half2 h = *reinterpret_cast<__half2*>(&out);
    return __half22float2(h);
}
__device__ __forceinline__ void stg_cs_v2(float* p, float a, float b) {
    asm volatile("st.global.cs.v2.f32 [%0], {%1, %2};"
                 :: "l"(p), "f"(a), "f"(b) : "memory");
}
__device__ __forceinline__ uint32_t fbits(float x) { return __float_as_uint(x); }

// cp.async helpers (sm_80 baseline PTX)
__device__ __forceinline__ void cp16(__half* sdst, const __half* gsrc) {
    uint32_t s;
    asm("{ .reg .u64 a; cvta.to.shared.u64 a, %1; cvt.u32.u64 %0, a; }"
        : "=r"(s) : "l"(sdst));
    asm volatile("cp.async.cg.shared.global [%0], [%1], 16;"
                 :: "r"(s), "l"(gsrc) : "memory");
}
#define CPASYNC_COMMIT() asm volatile("cp.async.commit_group;" ::: "memory")
#define CPASYNC_WAIT1()  asm volatile("cp.async.wait_group 1;" ::: "memory")
#define CPASYNC_WAIT0()  asm volatile("cp.async.wait_group 0;" ::: "memory")

// scale baked into Q fragments: 1/sqrt(64) * log2(e)
#define QSCALE 0.1803368801111204f

#define APAD 68
#define BPAD 72
#define HPAD 80   // half tile stride (halves); conflict-free for LDS.64 frags

// ===========================================================================
// Prep: fp32 K -> half Kh, pair-interleaved d within each 16-group.
// ===========================================================================
__global__ void k2h_kernel(const float* __restrict__ K, __half* __restrict__ Kh)
{
    int i = blockIdx.x * 256 + threadIdx.x;   // uint2 index
    int u = i & 3;
    int chunk = i >> 2;
    const float* src = K + (size_t)chunk * 16 + 2 * u;
    float2 lo = *(const float2*)src;
    float2 hi = *(const float2*)(src + 8);
    uint2 o;
    o.x = pack2(lo.x, lo.y);
    o.y = pack2(hi.x, hi.y);
    *(uint2*)((char*)Kh + (size_t)i * 8) = o;
}

// ===========================================================================
// Prep: fp32 V -> half Vt [kh][d][s_perm], s pair-interleaved per 16-group.
// ===========================================================================
__device__ __forceinline__ int perm16(int s) {
    int q = s & 15;
    int p = (q < 8) ? ((q >> 1) * 4 + (q & 1))
                    : (((q - 8) >> 1) * 4 + 2 + (q & 1));
    return (s & ~15) | p;
}

__global__ void vt_kernel(const float* __restrict__ V, __half* __restrict__ Vt)
{
    __shared__ float tile[32][33];
    const int kh = blockIdx.z;
    const int s0 = blockIdx.x * 32;
    const int d0 = blockIdx.y * 32;
    const int tx = threadIdx.x, ty = threadIdx.y;
#pragma unroll
    for (int i = 0; i < 32; i += 8)
        tile[ty + i][tx] = V[(size_t)(s0 + ty + i) * (HKV * HD) + kh * HD + d0 + tx];
    __syncthreads();
#pragma unroll
    for (int i = 0; i < 32; i += 8)
        Vt[(size_t)kh * HD * SEQ + (size_t)(d0 + ty + i) * SEQ + s0 + perm16(tx)] =
            __float2half_rn(tile[tx][ty + i]);
}

// ===========================================================================
// Q fragment loader (16 rows, scaled). Natural k-slot order.
// ===========================================================================
__device__ __forceinline__ void load_qfrag(
    uint32_t qf[4][4], const float* __restrict__ Q,
    int row0, int h, int g, int t4)
{
    const float* q0 = Q + (size_t)(row0 + g) * (HQ * HD) + h * HD;
    const float* q1 = q0 + (size_t)8 * (HQ * HD);
#pragma unroll
    for (int ks = 0; ks < 4; ks++) {
        int c = ks * 16 + t4 * 2;
        qf[ks][0] = pack2(q0[c] * QSCALE, q0[c + 1] * QSCALE);
        qf[ks][1] = pack2(q1[c] * QSCALE, q1[c + 1] * QSCALE);
        qf[ks][2] = pack2(q0[c + 8] * QSCALE, q0[c + 9] * QSCALE);
        qf[ks][3] = pack2(q1[c + 8] * QSCALE, q1[c + 9] * QSCALE);
    }
}

// B-fragment: one LDS.64 from pair-interleaved storage
__device__ __forceinline__ uint2 bfrag(const __half* base, int n, int ks, int t4) {
    return *(const uint2*)(base + n * HPAD + ks * 16 + t4 * 4);
}

// ===========================================================================
// Pass 1: partial rowsums. 128 thr, 4 warps x 16 rows = 64-row tile.
// grid (SEQ/64, HQ, RSPLIT). 128-key tiles, cp.async double buffer,
// f16x2 exponentials.
// ===========================================================================
__global__ __launch_bounds__(128) void rowsum_kernel(
    const float* __restrict__ Q, const __half* __restrict__ Kh,
    float* __restrict__ rspart)
{
    __shared__ __half Ks[2][128 * HPAD];

    const int t = threadIdx.x, lane = t & 31, wid = t >> 5;
    const int g = lane >> 2, t4 = lane & 3;
    const int m0 = blockIdx.x * 64, h = blockIdx.y, sp = blockIdx.z;
    const int kh = h / NREP;

    uint32_t qf[4][4];
    load_qfrag(qf, Q, m0 + wid * 16, h, g, t4);

    float rs0 = 0.f, rs1 = 0.f;
    const int it0 = sp * (SEQ / 128 / RSPLIT);
    const int it1 = it0 + (SEQ / 128 / RSPLIT);

    // issue first tile
    {
        const int n0 = it0 * 128;
#pragma unroll
        for (int i = 0; i < 8; i++) {
            int e = t + i * 128;
            int r = e >> 3, seg = e & 7;
            cp16(&Ks[0][r * HPAD + seg * 8],
                 Kh + (size_t)(n0 + r) * (HKV * HD) + kh * HD + seg * 8);
        }
        CPASYNC_COMMIT();
    }

    for (int it = it0; it < it1; it++) {
        const int buf = (it - it0) & 1;
        __syncthreads();   // all warps done with buf^1 before overwrite
        if (it + 1 < it1) {
            const int n0 = (it + 1) * 128;
#pragma unroll
            for (int i = 0; i < 8; i++) {
                int e = t + i * 128;
                int r = e >> 3, seg = e & 7;
                cp16(&Ks[buf ^ 1][r * HPAD + seg * 8],
                     Kh + (size_t)(n0 + r) * (HKV * HD) + kh * HD + seg * 8);
            }
            CPASYNC_COMMIT();
            CPASYNC_WAIT1();
        } else {
            CPASYNC_WAIT0();
        }
        __syncthreads();

        const __half* kb = Ks[buf];
#pragma unroll
        for (int jg = 0; jg < 2; jg++) {
#pragma unroll
            for (int j = 0; j < 8; j++) {
                float sacc[4] = {0.f, 0.f, 0.f, 0.f};
#pragma unroll
                for (int ks = 0; ks < 4; ks++) {
                    uint2 b = bfrag(kb, (jg * 8 + j) * 8 + g, ks, t4);
                    mma_f16(sacc, qf[ks], b.x, b.y);
                }
                float2 eA = ex2h2(sacc[0], sacc[1]);
                float2 eB = ex2h2(sacc[2], sacc[3]);
                rs0 += eA.x + eA.y;
                rs1 += eB.x + eB.y;
            }
        }
    }

    rs0 += __shfl_xor_sync(0xffffffffu, rs0, 1);
    rs0 += __shfl_xor_sync(0xffffffffu, rs0, 2);
    rs1 += __shfl_xor_sync(0xffffffffu, rs1, 1);
    rs1 += __shfl_xor_sync(0xffffffffu, rs1, 2);
    if (t4 == 0) {
        float* dst = rspart + (size_t)sp * HQ * SEQ + (size_t)h * SEQ + m0 + wid * 16;
        dst[g] = rs0;
        dst[g + 8] = rs1;
    }
}

// ===========================================================================
// Pass 2: fused scores + softmax write (.cs) + PV.
// 128 thr, 4 warps x 16 rows. grid (SEQ/64, HQ). cp.async double buffer.
// ===========================================================================
__global__ __launch_bounds__(128) void fused_att_kernel(
    const float* __restrict__ Q, const __half* __restrict__ Kh,
    const __half* __restrict__ Vt, const float* __restrict__ rspart,
    float* __restrict__ att, float* __restrict__ Ctx)
{
    __shared__ __half Ks[2][64 * HPAD];
    __shared__ __half Vs[2][64 * HPAD];
    __shared__ float sinv[64];

    const int t = threadIdx.x, lane = t & 31, wid = t >> 5;
    const int g = lane >> 2, t4 = lane & 3;
    const int m0 = blockIdx.x * 64, h = blockIdx.y;
    const int kh = h / NREP;

    if (t < 64) {
        const float* rp = rspart + (size_t)h * SEQ + m0 + t;
        float s = rp[0];
#pragma unroll
        for (int i = 1; i < RSPLIT; i++) s += rp[(size_t)i * HQ * SEQ];
        sinv[t] = 1.0f / s;
    }

    uint32_t qf[4][4];
    load_qfrag(qf, Q, m0 + wid * 16, h, g, t4);

    const __half* vth = Vt + (size_t)kh * HD * SEQ;

    // issue first K/V tile
    {
#pragma unroll
        for (int i = 0; i < 4; i++) {
            int e = t + i * 128;
            int r = e >> 3, seg = e & 7;
            cp16(&Ks[0][r * HPAD + seg * 8],
                 Kh + (size_t)r * (HKV * HD) + kh * HD + seg * 8);
            cp16(&Vs[0][r * HPAD + seg * 8],
                 vth + (size_t)r * SEQ + seg * 8);
        }
        CPASYNC_COMMIT();
    }
    __syncthreads();   // sinv visible

    const int rl = wid * 16 + g;
    const float inv_lo = sinv[rl];
    const float inv_hi = sinv[rl + 8];

    float ctx[8][4];
#pragma unroll
    for (int j = 0; j < 8; j++)
#pragma unroll
        for (int c = 0; c < 4; c++) ctx[j][c] = 0.f;

    float* atth = att + (size_t)h * SEQ * SEQ;

    for (int it = 0; it < SEQ / 64; it++) {
        const int buf = it & 1;
        __syncthreads();   // all warps done with buf^1
        if (it + 1 < SEQ / 64) {
            const int k0n = (it + 1) * 64;
#pragma unroll
            for (int i = 0; i < 4; i++) {
                int e = t + i * 128;
                int r = e >> 3, seg = e & 7;
                cp16(&Ks[buf ^ 1][r * HPAD + seg * 8],
                     Kh + (size_t)(k0n + r) * (HKV * HD) + kh * HD + seg * 8);
                cp16(&Vs[buf ^ 1][r * HPAD + seg * 8],
                     vth + (size_t)r * SEQ + k0n + seg * 8);
            }
            CPASYNC_COMMIT();
            CPASYNC_WAIT1();
        } else {
            CPASYNC_WAIT0();
        }
        __syncthreads();

        const __half* kb = Ks[buf];
        const __half* vb = Vs[buf];
        const int k0 = it * 64;

        // scores: 16 rows x 64 keys
        float sacc[8][4];
#pragma unroll
        for (int j = 0; j < 8; j++)
#pragma unroll
            for (int c = 0; c < 4; c++) sacc[j][c] = 0.f;

#pragma unroll
        for (int ks = 0; ks < 4; ks++) {
#pragma unroll
            for (int j = 0; j < 8; j++) {
                uint2 b = bfrag(kb, j * 8 + g, ks, t4);
                mma_f16(sacc[j], qf[ks], b.x, b.y);
            }
        }

        // epilogue: p = ex2(sacc)*inv -> att (.cs), pack to fp16 A-frags
        const size_t rowbase = (size_t)(m0 + rl) * SEQ + k0;
        uint32_t pk[8][2];
#pragma unroll
        for (int j = 0; j < 8; j++) {
            float p0 = ex2(sacc[j][0]) * inv_lo;
            float p1 = ex2(sacc[j][1]) * inv_lo;
            float p2 = ex2(sacc[j][2]) * inv_hi;
            float p3 = ex2(sacc[j][3]) * inv_hi;
            int cj = j * 8 + t4 * 2;
            stg_cs_v2(atth + rowbase + cj, p0, p1);
            stg_cs_v2(atth + rowbase + 8 * SEQ + cj, p2, p3);
            pk[j][0] = pack2(p0, p1);
            pk[j][1] = pack2(p2, p3);
        }

        // PV: A-frags = packed score C-frags (natural key slots)
#pragma unroll
        for (int kc = 0; kc < 4; kc++) {
            uint32_t A[4] = { pk[2 * kc][0], pk[2 * kc][1],
                              pk[2 * kc + 1][0], pk[2 * kc + 1][1] };
#pragma unroll
            for (int jj = 0; jj < 8; jj++) {
                uint2 b = bfrag(vb, jj * 8 + g, kc, t4);
                mma_f16(ctx[jj], A, b.x, b.y);
            }
        }
    }

    // store context
#pragma unroll
    for (int jj = 0; jj < 8; jj++) {
        int col = h * HD + jj * 8 + t4 * 2;
        *(float2*)(Ctx + (size_t)(m0 + rl) * (HQ * HD) + col) =
            make_float2(ctx[jj][0], ctx[jj][1]);
        *(float2*)(Ctx + (size_t)(m0 + rl + 8) * (HQ * HD) + col) =
            make_float2(ctx[jj][2], ctx[jj][3]);
    }
}

// ===========================================================================
// Projections (tf32 mma, round-9 shape): C[M,N] = A[M,K] @ B[K,N] + bias
// BM=128 x BN=64, BK=64. 256 thr, warps 4(m) x 2(n).
// ===========================================================================
#define PJ_AS 0
#define PJ_BS (128 * APAD)
#define PJ_SMEM_BYTES ((PJ_BS + 64 * BPAD) * 4)

__device__ __forceinline__ void proj_mma_stage(
    float* As, float* Bs, float acc[2][4][4],
    int wm, int wn, int g, int t4)
{
#pragma unroll
    for (int ks = 0; ks < 8; ks++) {
        const int kk = ks * 8;
        uint32_t Bf[4][2];
#pragma unroll
        for (int j = 0; j < 4; j++) {
            int n = wn * 32 + j * 8 + g;
            Bf[j][0] = fbits(Bs[(kk + t4) * BPAD + n]);
            Bf[j][1] = fbits(Bs[(kk + t4 + 4) * BPAD + n]);
        }
#pragma unroll
        for (int i = 0; i < 2; i++) {
            int r = wm * 32 + i * 16 + g;
            uint32_t Af[4] = {
                fbits(As[r * APAD + kk + t4]),
                fbits(As[(r + 8) * APAD + kk + t4]),
                fbits(As[r * APAD + kk + t4 + 4]),
                fbits(As[(r + 8) * APAD + kk + t4 + 4]) };
#pragma unroll
            for (int j = 0; j < 4; j++) mma_tf32(acc[i][j], Af, Bf[j]);
        }
    }
}

__device__ __forceinline__ void proj_epilogue(
    float acc[2][4][4], const float* bias, float* C, int ldc,
    int m0, int n0, int wm, int wn, int g, int t4)
{
#pragma unroll
    for (int i = 0; i < 2; i++) {
        int r0 = m0 + wm * 32 + i * 16 + g;
#pragma unroll
        for (int j = 0; j < 4; j++) {
            int col = n0 + wn * 32 + j * 8 + t4 * 2;
            float b0 = bias[col], b1 = bias[col + 1];
            *(float2*)(C + (size_t)r0 * ldc + col) =
                make_float2(acc[i][j][0] + b0, acc[i][j][1] + b1);
            *(float2*)(C + (size_t)(r0 + 8) * ldc + col) =
                make_float2(acc[i][j][2] + b0, acc[i][j][3] + b1);
        }
    }
}

__device__ __forceinline__ void proj_body(
    const float* __restrict__ A, int lda,
    const float* __restrict__ B, int ldb,
    const float* __restrict__ bias,
    float* __restrict__ C, int ldc, int Kdim, int m0, int n0)
{
    extern __shared__ float sm[];
    float* As = sm + PJ_AS;
    float* Bs = sm + PJ_BS;

    const int t = threadIdx.x, lane = t & 31, wid = t >> 5;
    const int wm = wid >> 1, wn = wid & 1;
    const int g = lane >> 2, t4 = lane & 3;

    float acc[2][4][4];
#pragma unroll
    for (int i = 0; i < 2; i++)
#pragma unroll
        for (int j = 0; j < 4; j++)
#pragma unroll
            for (int c = 0; c < 4; c++) acc[i][j][c] = 0.f;

    for (int k0 = 0; k0 < Kdim; k0 += 64) {
        float4 av[8];
#pragma unroll
        for (int i = 0; i < 8; i++) {
            int e = t + i * 256;
            int r = e >> 4, q = e & 15;
            av[i] = tf32x4(*(const float4*)(A + (size_t)(m0 + r) * lda + k0 + q * 4));
        }
        float4 bv[4];
#pragma unroll
        for (int i = 0; i < 4; i++) {
            int e = t + i * 256;
            int r = e >> 4, q = e & 15;
            bv[i] = tf32x4(*(const float4*)(B + (size_t)(k0 + r) * ldb + n0 + q * 4));
        }
        __syncthreads();
#pragma unroll
        for (int i = 0; i < 8; i++) {
            int e = t + i * 256;
            int r = e >> 4, q = e & 15;
            *(float4*)&As[r * APAD + q * 4] = av[i];
        }
#pragma unroll
        for (int i = 0; i < 4; i++) {
            int e = t + i * 256;
            int r = e >> 4, q = e & 15;
            *(float4*)&Bs[r * BPAD + q * 4] = bv[i];
        }
        __syncthreads();
        proj_mma_stage(As, Bs, acc, wm, wn, g, t4);
        __syncthreads();
    }
    proj_epilogue(acc, bias, C, ldc, m0, n0, wm, wn, g, t4);
}

__global__ __launch_bounds__(256, 2) void qkv_proj_kernel(
    const float* __restrict__ x,
    const float* __restrict__ Wq, const float* __restrict__ bq,
    const float* __restrict__ Wk, const float* __restrict__ bk,
    const float* __restrict__ Wv, const float* __restrict__ bv,
    float* __restrict__ Qo, float* __restrict__ Ko, float* __restrict__ Vo)
{
    const int seg = blockIdx.x;
    const int m0 = blockIdx.y * 128;
    const float *W, *bias;
    float* C;
    int ld, n0;
    if (seg < 8)       { W = Wq; bias = bq; C = Qo; ld = HQ * HD;  n0 = seg * 64; }
    else if (seg < 10) { W = Wk; bias = bk; C = Ko; ld = HKV * HD; n0 = (seg - 8) * 64; }
    else               { W = Wv; bias = bv; C = Vo; ld = HKV * HD; n0 = (seg - 10) * 64; }
    proj_body(x, DIMX, W, ld, bias, C, ld, DIMX, m0, n0);
}

__global__ __launch_bounds__(256, 2) void out_proj_kernel(
    const float* __restrict__ Ctx, const float* __restrict__ Wo,
    const float* __restrict__ bo, float* __restrict__ out)
{
    proj_body(Ctx, HQ * HD, Wo, DIMX, bo, out, DIMX, HQ * HD,
              blockIdx.y * 128, blockIdx.x * 64);
}

// ===========================================================================
extern "C" void kernel_launch(void* const* d_in, const int* in_sizes, int n_in,
                              void* d_out, int out_size)
{
    const float* x  = (const float*)d_in[0];
    const float* Wq = (const float*)d_in[1];
    const float* bq = (const float*)d_in[2];
    const float* Wk = (const float*)d_in[3];
    const float* bk = (const float*)d_in[4];
    const float* Wv = (const float*)d_in[5];
    const float* bv = (const float*)d_in[6];
    const float* Wo = (const float*)d_in[7];
    const float* bo = (const float*)d_in[8];

    float* out = (float*)d_out;                 // [4096, 768]
    float* att = out + (size_t)SEQ * DIMX;      // [8, 4096, 4096]

    void* p;
    cudaGetSymbolAddress(&p, g_Q);      float*  Qp  = (float*)p;
    cudaGetSymbolAddress(&p, g_K);      float*  Kp  = (float*)p;
    cudaGetSymbolAddress(&p, g_V);      float*  Vp  = (float*)p;
    cudaGetSymbolAddress(&p, g_Kh);     __half* Khp = (__half*)p;
    cudaGetSymbolAddress(&p, g_Vt);     __half* Vtp = (__half*)p;
    cudaGetSymbolAddress(&p, g_C);      float*  Cp  = (float*)p;
    cudaGetSymbolAddress(&p, g_rspart); float*  Rpp = (float*)p;

    cudaFuncSetAttribute(qkv_proj_kernel,
        cudaFuncAttributeMaxDynamicSharedMemorySize, PJ_SMEM_BYTES);
    cudaFuncSetAttribute(out_proj_kernel,
        cudaFuncAttributeMaxDynamicSharedMemorySize, PJ_SMEM_BYTES);

    // QKV projections (round-9 shape)
    qkv_proj_kernel<<<dim3(12, SEQ / 128), 256, PJ_SMEM_BYTES>>>(
        x, Wq, bq, Wk, bk, Wv, bv, Qp, Kp, Vp);

    // preps (pair-interleaved layouts)
    k2h_kernel<<<(SEQ * HKV * HD) / 4 / 256, 256>>>(Kp, Khp);
    vt_kernel<<<dim3(SEQ / 32, HD / 32, HKV), dim3(32, 8)>>>(Vp, Vtp);

    // Pass 1: partial rowsums (cp.async pipeline + f16x2 ex2)
    rowsum_kernel<<<dim3(SEQ / 64, HQ, RSPLIT), 128>>>(Qp, Khp, Rpp);

    // Pass 2: fused scores + softmax write + PV (cp.async pipeline)
    fused_att_kernel<<<dim3(SEQ / 64, HQ), 128>>>(Qp, Khp, Vtp, Rpp, att, Cp);

    // out = ctx @ Wo + bo (round-9 shape)
    out_proj_kernel<<<dim3(DIMX / 64, SEQ / 128), 256, PJ_SMEM_BYTES>>>(
        Cp, Wo, bo, out);
}

// round 13
// speedup vs baseline: 1.1159x; 1.0170x over previous
#include <cuda_runtime.h>
#include <cuda_fp16.h>
#include <cstdint>

// Problem constants
#define DIMX 768
#define HQ   8
#define HKV  2
#define HD   64
#define SEQ  4096
#define NREP (HQ / HKV)   // 4
#define RSPLIT 4          // rowsum key split

// Scratch (allocation-free rule: __device__ globals)
__device__ float  g_Q[SEQ * HQ * HD];           // fp32
__device__ float  g_K[SEQ * HKV * HD];          // fp32
__device__ float  g_V[SEQ * HKV * HD];          // fp32
__device__ __half g_Kh[SEQ * HKV * HD];         // half, pair-interleaved d
__device__ __half g_Vt[HKV * HD * SEQ];         // [2][64][4096] half, transposed, pair-interleaved s
__device__ float  g_C[SEQ * HQ * HD];           // context
__device__ float  g_rspart[RSPLIT * HQ * SEQ];  // rowsum partials

// ===========================================================================
// helpers
// ===========================================================================
__device__ __forceinline__ float f2tf32(float x) {
    uint32_t u;
    asm("cvt.rna.tf32.f32 %0, %1;" : "=r"(u) : "f"(x));
    return __uint_as_float(u);
}
__device__ __forceinline__ float4 tf32x4(float4 v) {
    float4 w;
    w.x = f2tf32(v.x); w.y = f2tf32(v.y); w.z = f2tf32(v.z); w.w = f2tf32(v.w);
    return w;
}
__device__ __forceinline__ void mma_tf32(float* c, const uint32_t* a, const uint32_t* b) {
    asm volatile(
        "mma.sync.aligned.m16n8k8.row.col.f32.tf32.tf32.f32 "
        "{%0,%1,%2,%3}, {%4,%5,%6,%7}, {%8,%9}, {%0,%1,%2,%3};"
        : "+f"(c[0]), "+f"(c[1]), "+f"(c[2]), "+f"(c[3])
        : "r"(a[0]), "r"(a[1]), "r"(a[2]), "r"(a[3]), "r"(b[0]), "r"(b[1]));
}
__device__ __forceinline__ void mma_f16(float* c, const uint32_t* a, uint32_t b0, uint32_t b1) {
    asm volatile(
        "mma.sync.aligned.m16n8k16.row.col.f32.f16.f16.f32 "
        "{%0,%1,%2,%3}, {%4,%5,%6,%7}, {%8,%9}, {%0,%1,%2,%3};"
        : "+f"(c[0]), "+f"(c[1]), "+f"(c[2]), "+f"(c[3])
        : "r"(a[0]), "r"(a[1]), "r"(a[2]), "r"(a[3]), "r"(b0), "r"(b1));
}
__device__ __forceinline__ uint32_t pack2(float a, float b) {
    __half2 h = __floats2half2_rn(a, b);
    return *reinterpret_cast<uint32_t*>(&h);
}
__device__ __forceinline__ float ex2(float x) {
    float y;
    asm("ex2.approx.f32 %0, %1;" : "=f"(y) : "f"(x));
    return y;
}
// two exponentials in one MUFU op (fp16x2); returns fp32 pair
__device__ __forceinline__ float2 ex2h2(float a, float b) {
    uint32_t in = pack2(a, b);
    uint32_t out;
    asm("ex2.approx.f16x2 %0, %1;" : "=r"(out) : "r"(in));
    __half2 h = *reinterpret_cast<__half2*>(&out);
    return __half22float2(h);
}
__device__ __forceinline__ void stg_cs_v2(float* p, float a, float b) {
    asm volatile("st.global.cs.v2.f32 [%0], {%1, %2};"
                 :: "l"(p), "f"(a), "f"(b) : "memory");
}
__device__ __forceinline__ uint32_t fbits(float x) { return __float_as_uint(x); }

// cp.async helpers (sm_80 baseline PTX)
__device__ __forceinline__ void cp16(__half* sdst, const __half* gsrc) {
    uint32_t s;
    asm("{ .reg .u64 a; cvta.to.shared.u64 a, %1; cvt.u32.u64 %0, a; }"
        : "=r"(s) : "l"(sdst));
    asm volatile("cp.async.cg.shared.global [%0], [%1], 16;"
                 :: "r"(s), "l"(gsrc) : "memory");
}
#define CPASYNC_COMMIT() asm volatile("cp.async.commit_group;" ::: "memory")
#define CPASYNC_WAIT1()  asm volatile("cp.async.wait_group 1;" ::: "memory")
#define CPASYNC_WAIT0()  asm volatile("cp.async.wait_group 0;" ::: "memory")

// scale baked into Q fragments: 1/sqrt(64) * log2(e)
#define QSCALE 0.1803368801111204f

#define APAD 68
#define BPAD 72
#define HPAD 80   // half tile stride (halves); conflict-free for LDS.64 frags

// ===========================================================================
// Prep: fp32 K -> half Kh, pair-interleaved d within each 16-group.
// ===========================================================================
__global__ void k2h_kernel(const float* __restrict__ K, __half* __restrict__ Kh)
{
    int i = blockIdx.x * 256 + threadIdx.x;   // uint2 index
    int u = i & 3;
    int chunk = i >> 2;
    const float* src = K + (size_t)chunk * 16 + 2 * u;
    float2 lo = *(const float2*)src;
    float2 hi = *(const float2*)(src + 8);
    uint2 o;
    o.x = pack2(lo.x, lo.y);
    o.y = pack2(hi.x, hi.y);
    *(uint2*)((char*)Kh + (size_t)i * 8) = o;
}

// ===========================================================================
// Prep: fp32 V -> half Vt [kh][d][s_perm], s pair-interleaved per 16-group.
// ===========================================================================
__device__ __forceinline__ int perm16(int s) {
    int q = s & 15;
    int p = (q < 8) ? ((q >> 1) * 4 + (q & 1))
                    : (((q - 8) >> 1) * 4 + 2 + (q & 1));
    return (s & ~15) | p;
}

__global__ void vt_kernel(const float* __restrict__ V, __half* __restrict__ Vt)
{
    __shared__ float tile[32][33];
    const int kh = blockIdx.z;
    const int s0 = blockIdx.x * 32;
    const int d0 = blockIdx.y * 32;
    const int tx = threadIdx.x, ty = threadIdx.y;
#pragma unroll
    for (int i = 0; i < 32; i += 8)
        tile[ty + i][tx] = V[(size_t)(s0 + ty + i) * (HKV * HD) + kh * HD + d0 + tx];
    __syncthreads();
#pragma unroll
    for (int i = 0; i < 32; i += 8)
        Vt[(size_t)kh * HD * SEQ + (size_t)(d0 + ty + i) * SEQ + s0 + perm16(tx)] =
            __float2half_rn(tile[tx][ty + i]);
}

// ===========================================================================
// Q fragment loader (16 rows, scaled). Natural k-slot order.
// ===========================================================================
__device__ __forceinline__ void load_qfrag(
    uint32_t qf[4][4], const float* __restrict__ Q,
    int row0, int h, int g, int t4)
{
    const float* q0 = Q + (size_t)(row0 + g) * (HQ * HD) + h * HD;
    const float* q1 = q0 + (size_t)8 * (HQ * HD);
#pragma unroll
    for (int ks = 0; ks < 4; ks++) {
        int c = ks * 16 + t4 * 2;
        qf[ks][0] = pack2(q0[c] * QSCALE, q0[c + 1] * QSCALE);
        qf[ks][1] = pack2(q1[c] * QSCALE, q1[c + 1] * QSCALE);
        qf[ks][2] = pack2(q0[c + 8] * QSCALE, q0[c + 9] * QSCALE);
        qf[ks][3] = pack2(q1[c + 8] * QSCALE, q1[c + 9] * QSCALE);
    }
}

// B-fragment: one LDS.64 from pair-interleaved storage
__device__ __forceinline__ uint2 bfrag(const __half* base, int n, int ks, int t4) {
    return *(const uint2*)(base + n * HPAD + ks * 16 + t4 * 4);
}

// ===========================================================================
// Pass 1: partial rowsums. 128 thr, 4 warps x 16 rows = 64-row tile.
// grid (SEQ/64, HQ, RSPLIT). 64-key tiles, cp.async double buffer (20.5KB),
// f16x2 exponentials. launch_bounds(128,8) for high occupancy.
// ===========================================================================
__global__ __launch_bounds__(128, 8) void rowsum_kernel(
    const float* __restrict__ Q, const __half* __restrict__ Kh,
    float* __restrict__ rspart)
{
    __shared__ __half Ks[2][64 * HPAD];

    const int t = threadIdx.x, lane = t & 31, wid = t >> 5;
    const int g = lane >> 2, t4 = lane & 3;
    const int m0 = blockIdx.x * 64, h = blockIdx.y, sp = blockIdx.z;
    const int kh = h / NREP;

    uint32_t qf[4][4];
    load_qfrag(qf, Q, m0 + wid * 16, h, g, t4);

    float rs0 = 0.f, rs1 = 0.f;
    const int it0 = sp * (SEQ / 64 / RSPLIT);
    const int it1 = it0 + (SEQ / 64 / RSPLIT);

    // issue first tile (64 keys)
    {
        const int n0 = it0 * 64;
#pragma unroll
        for (int i = 0; i < 4; i++) {
            int e = t + i * 128;
            int r = e >> 3, seg = e & 7;
            cp16(&Ks[0][r * HPAD + seg * 8],
                 Kh + (size_t)(n0 + r) * (HKV * HD) + kh * HD + seg * 8);
        }
        CPASYNC_COMMIT();
    }

    for (int it = it0; it < it1; it++) {
        const int buf = (it - it0) & 1;
        __syncthreads();   // all warps done with buf^1 before overwrite
        if (it + 1 < it1) {
            const int n0 = (it + 1) * 64;
#pragma unroll
            for (int i = 0; i < 4; i++) {
                int e = t + i * 128;
                int r = e >> 3, seg = e & 7;
                cp16(&Ks[buf ^ 1][r * HPAD + seg * 8],
                     Kh + (size_t)(n0 + r) * (HKV * HD) + kh * HD + seg * 8);
            }
            CPASYNC_COMMIT();
            CPASYNC_WAIT1();
        } else {
            CPASYNC_WAIT0();
        }
        __syncthreads();

        const __half* kb = Ks[buf];
#pragma unroll
        for (int j = 0; j < 8; j++) {
            float sacc[4] = {0.f, 0.f, 0.f, 0.f};
#pragma unroll
            for (int ks = 0; ks < 4; ks++) {
                uint2 b = bfrag(kb, j * 8 + g, ks, t4);
                mma_f16(sacc, qf[ks], b.x, b.y);
            }
            float2 eA = ex2h2(sacc[0], sacc[1]);
            float2 eB = ex2h2(sacc[2], sacc[3]);
            rs0 += eA.x + eA.y;
            rs1 += eB.x + eB.y;
        }
    }

    rs0 += __shfl_xor_sync(0xffffffffu, rs0, 1);
    rs0 += __shfl_xor_sync(0xffffffffu, rs0, 2);
    rs1 += __shfl_xor_sync(0xffffffffu, rs1, 1);
    rs1 += __shfl_xor_sync(0xffffffffu, rs1, 2);
    if (t4 == 0) {
        float* dst = rspart + (size_t)sp * HQ * SEQ + (size_t)h * SEQ + m0 + wid * 16;
        dst[g] = rs0;
        dst[g + 8] = rs1;
    }
}

// ===========================================================================
// Pass 2: fused scores + softmax write (.cs) + PV.
// 128 thr, 4 warps x 16 rows. grid (SEQ/64, HQ). cp.async double buffer.
// ===========================================================================
__global__ __launch_bounds__(128) void fused_att_kernel(
    const float* __restrict__ Q, const __half* __restrict__ Kh,
    const __half* __restrict__ Vt, const float* __restrict__ rspart,
    float* __restrict__ att, float* __restrict__ Ctx)
{
    __shared__ __half Ks[2][64 * HPAD];
    __shared__ __half Vs[2][64 * HPAD];
    __shared__ float sinv[64];

    const int t = threadIdx.x, lane = t & 31, wid = t >> 5;
    const int g = lane >> 2, t4 = lane & 3;
    const int m0 = blockIdx.x * 64, h = blockIdx.y;
    const int kh = h / NREP;

    if (t < 64) {
        const float* rp = rspart + (size_t)h * SEQ + m0 + t;
        float s = rp[0];
#pragma unroll
        for (int i = 1; i < RSPLIT; i++) s += rp[(size_t)i * HQ * SEQ];
        sinv[t] = 1.0f / s;
    }

    uint32_t qf[4][4];
    load_qfrag(qf, Q, m0 + wid * 16, h, g, t4);

    const __half* vth = Vt + (size_t)kh * HD * SEQ;

    // issue first K/V tile
    {
#pragma unroll
        for (int i = 0; i < 4; i++) {
            int e = t + i * 128;
            int r = e >> 3, seg = e & 7;
            cp16(&Ks[0][r * HPAD + seg * 8],
                 Kh + (size_t)r * (HKV * HD) + kh * HD + seg * 8);
            cp16(&Vs[0][r * HPAD + seg * 8],
                 vth + (size_t)r * SEQ + seg * 8);
        }
        CPASYNC_COMMIT();
    }
    __syncthreads();   // sinv visible

    const int rl = wid * 16 + g;
    const float inv_lo = sinv[rl];
    const float inv_hi = sinv[rl + 8];

    float ctx[8][4];
#pragma unroll
    for (int j = 0; j < 8; j++)
#pragma unroll
        for (int c = 0; c < 4; c++) ctx[j][c] = 0.f;

    float* atth = att + (size_t)h * SEQ * SEQ;

    for (int it = 0; it < SEQ / 64; it++) {
        const int buf = it & 1;
        __syncthreads();   // all warps done with buf^1
        if (it + 1 < SEQ / 64) {
            const int k0n = (it + 1) * 64;
#pragma unroll
            for (int i = 0; i < 4; i++) {
                int e = t + i * 128;
                int r = e >> 3, seg = e & 7;
                cp16(&Ks[buf ^ 1][r * HPAD + seg * 8],
                     Kh + (size_t)(k0n + r) * (HKV * HD) + kh * HD + seg * 8);
                cp16(&Vs[buf ^ 1][r * HPAD + seg * 8],
                     vth + (size_t)r * SEQ + k0n + seg * 8);
            }
            CPASYNC_COMMIT();
            CPASYNC_WAIT1();
        } else {
            CPASYNC_WAIT0();
        }
        __syncthreads();

        const __half* kb = Ks[buf];
        const __half* vb = Vs[buf];
        const int k0 = it * 64;

        // scores: 16 rows x 64 keys
        float sacc[8][4];
#pragma unroll
        for (int j = 0; j < 8; j++)
#pragma unroll
            for (int c = 0; c < 4; c++) sacc[j][c] = 0.f;

#pragma unroll
        for (int ks = 0; ks < 4; ks++) {
#pragma unroll
            for (int j = 0; j < 8; j++) {
                uint2 b = bfrag(kb, j * 8 + g, ks, t4);
                mma_f16(sacc[j], qf[ks], b.x, b.y);
            }
        }

        // epilogue: p = ex2(sacc)*inv -> att (.cs), pack to fp16 A-frags
        const size_t rowbase = (size_t)(m0 + rl) * SEQ + k0;
        uint32_t pk[8][2];
#pragma unroll
        for (int j = 0; j < 8; j++) {
            float p0 = ex2(sacc[j][0]) * inv_lo;
            float p1 = ex2(sacc[j][1]) * inv_lo;
            float p2 = ex2(sacc[j][2]) * inv_hi;
            float p3 = ex2(sacc[j][3]) * inv_hi;
            int cj = j * 8 + t4 * 2;
            stg_cs_v2(atth + rowbase + cj, p0, p1);
            stg_cs_v2(atth + rowbase + 8 * SEQ + cj, p2, p3);
            pk[j][0] = pack2(p0, p1);
            pk[j][1] = pack2(p2, p3);
        }

        // PV: A-frags = packed score C-frags (natural key slots)
#pragma unroll
        for (int kc = 0; kc < 4; kc++) {
            uint32_t A[4] = { pk[2 * kc][0], pk[2 * kc][1],
                              pk[2 * kc + 1][0], pk[2 * kc + 1][1] };
#pragma unroll
            for (int jj = 0; jj < 8; jj++) {
                uint2 b = bfrag(vb, jj * 8 + g, kc, t4);
                mma_f16(ctx[jj], A, b.x, b.y);
            }
        }
    }

    // store context
#pragma unroll
    for (int jj = 0; jj < 8; jj++) {
        int col = h * HD + jj * 8 + t4 * 2;
        *(float2*)(Ctx + (size_t)(m0 + rl) * (HQ * HD) + col) =
            make_float2(ctx[jj][0], ctx[jj][1]);
        *(float2*)(Ctx + (size_t)(m0 + rl + 8) * (HQ * HD) + col) =
            make_float2(ctx[jj][2], ctx[jj][3]);
    }
}

// ===========================================================================
// Projections (tf32 mma): C[M,N] = A[M,K] @ B[K,N] + bias
// BM=128 x BN=64, BK=64. 256 thr, warps 4(m) x 2(n). launch_bounds(256,3).
// ===========================================================================
#define PJ_AS 0
#define PJ_BS (128 * APAD)
#define PJ_SMEM_BYTES ((PJ_BS + 64 * BPAD) * 4)

__device__ __forceinline__ void proj_mma_stage(
    float* As, float* Bs, float acc[2][4][4],
    int wm, int wn, int g, int t4)
{
#pragma unroll
    for (int ks = 0; ks < 8; ks++) {
        const int kk = ks * 8;
        uint32_t Bf[4][2];
#pragma unroll
        for (int j = 0; j < 4; j++) {
            int n = wn * 32 + j * 8 + g;
            Bf[j][0] = fbits(Bs[(kk + t4) * BPAD + n]);
            Bf[j][1] = fbits(Bs[(kk + t4 + 4) * BPAD + n]);
        }
#pragma unroll
        for (int i = 0; i < 2; i++) {
            int r = wm * 32 + i * 16 + g;
            uint32_t Af[4] = {
                fbits(As[r * APAD + kk + t4]),
                fbits(As[(r + 8) * APAD + kk + t4]),
                fbits(As[r * APAD + kk + t4 + 4]),
                fbits(As[(r + 8) * APAD + kk + t4 + 4]) };
#pragma unroll
            for (int j = 0; j < 4; j++) mma_tf32(acc[i][j], Af, Bf[j]);
        }
    }
}

__device__ __forceinline__ void proj_epilogue(
    float acc[2][4][4], const float* bias, float* C, int ldc,
    int m0, int n0, int wm, int wn, int g, int t4)
{
#pragma unroll
    for (int i = 0; i < 2; i++) {
        int r0 = m0 + wm * 32 + i * 16 + g;
#pragma unroll
        for (int j = 0; j < 4; j++) {
            int col = n0 + wn * 32 + j * 8 + t4 * 2;
            float b0 = bias[col], b1 = bias[col + 1];
            *(float2*)(C + (size_t)r0 * ldc + col) =
                make_float2(acc[i][j][0] + b0, acc[i][j][1] + b1);
            *(float2*)(C + (size_t)(r0 + 8) * ldc + col) =
                make_float2(acc[i][j][2] + b0, acc[i][j][3] + b1);
        }
    }
}

__device__ __forceinline__ void proj_body(
    const float* __restrict__ A, int lda,
    const float* __restrict__ B, int ldb,
    const float* __restrict__ bias,
    float* __restrict__ C, int ldc, int Kdim, int m0, int n0)
{
    extern __shared__ float sm[];
    float* As = sm + PJ_AS;
    float* Bs = sm + PJ_BS;

    const int t = threadIdx.x, lane = t & 31, wid = t >> 5;
    const int wm = wid >> 1, wn = wid & 1;
    const int g = lane >> 2, t4 = lane & 3;

    float acc[2][4][4];
#pragma unroll
    for (int i = 0; i < 2; i++)
#pragma unroll
        for (int j = 0; j < 4; j++)
#pragma unroll
            for (int c = 0; c < 4; c++) acc[i][j][c] = 0.f;

    for (int k0 = 0; k0 < Kdim; k0 += 64) {
        float4 av[8];
#pragma unroll
        for (int i = 0; i < 8; i++) {
            int e = t + i * 256;
            int r = e >> 4, q = e & 15;
            av[i] = tf32x4(*(const float4*)(A + (size_t)(m0 + r) * lda + k0 + q * 4));
        }
        float4 bv[4];
#pragma unroll
        for (int i = 0; i < 4; i++) {
            int e = t + i * 256;
            int r = e >> 4, q = e & 15;
            bv[i] = tf32x4(*(const float4*)(B + (size_t)(k0 + r) * ldb + n0 + q * 4));
        }
        __syncthreads();
#pragma unroll
        for (int i = 0; i < 8; i++) {
            int e = t + i * 256;
            int r = e >> 4, q = e & 15;
            *(float4*)&As[r * APAD + q * 4] = av[i];
        }
#pragma unroll
        for (int i = 0; i < 4; i++) {
            int e = t + i * 256;
            int r = e >> 4, q = e & 15;
            *(float4*)&Bs[r * BPAD + q * 4] = bv[i];
        }
        __syncthreads();
        proj_mma_stage(As, Bs, acc, wm, wn, g, t4);
        __syncthreads();
    }
    proj_epilogue(acc, bias, C, ldc, m0, n0, wm, wn, g, t4);
}

__global__ __launch_bounds__(256, 3) void qkv_proj_kernel(
    const float* __restrict__ x,
    const float* __restrict__ Wq, const float* __restrict__ bq,
    const float* __restrict__ Wk, const float* __restrict__ bk,
    const float* __restrict__ Wv, const float* __restrict__ bv,
    float* __restrict__ Qo, float* __restrict__ Ko, float* __restrict__ Vo)
{
    const int seg = blockIdx.x;
    const int m0 = blockIdx.y * 128;
    const float *W, *bias;
    float* C;
    int ld, n0;
    if (seg < 8)       { W = Wq; bias = bq; C = Qo; ld = HQ * HD;  n0 = seg * 64; }
    else if (seg < 10) { W = Wk; bias = bk; C = Ko; ld = HKV * HD; n0 = (seg - 8) * 64; }
    else               { W = Wv; bias = bv; C = Vo; ld = HKV * HD; n0 = (seg - 10) * 64; }
    proj_body(x, DIMX, W, ld, bias, C, ld, DIMX, m0, n0);
}

__global__ __launch_bounds__(256, 3) void out_proj_kernel(
    const float* __restrict__ Ctx, const float* __restrict__ Wo,
    const float* __restrict__ bo, float* __restrict__ out)
{
    proj_body(Ctx, HQ * HD, Wo, DIMX, bo, out, DIMX, HQ * HD,
              blockIdx.y * 128, blockIdx.x * 64);
}

// ===========================================================================
extern "C" void kernel_launch(void* const* d_in, const int* in_sizes, int n_in,
                              void* d_out, int out_size)
{
    const float* x  = (const float*)d_in[0];
    const float* Wq = (const float*)d_in[1];
    const float* bq = (const float*)d_in[2];
    const float* Wk = (const float*)d_in[3];
    const float* bk = (const float*)d_in[4];
    const float* Wv = (const float*)d_in[5];
    const float* bv = (const float*)d_in[6];
    const float* Wo = (const float*)d_in[7];
    const float* bo = (const float*)d_in[8];

    float* out = (float*)d_out;                 // [4096, 768]
    float* att = out + (size_t)SEQ * DIMX;      // [8, 4096, 4096]

    void* p;
    cudaGetSymbolAddress(&p, g_Q);      float*  Qp  = (float*)p;
    cudaGetSymbolAddress(&p, g_K);      float*  Kp  = (float*)p;
    cudaGetSymbolAddress(&p, g_V);      float*  Vp  = (float*)p;
    cudaGetSymbolAddress(&p, g_Kh);     __half* Khp = (__half*)p;
    cudaGetSymbolAddress(&p, g_Vt);     __half* Vtp = (__half*)p;
    cudaGetSymbolAddress(&p, g_C);      float*  Cp  = (float*)p;
    cudaGetSymbolAddress(&p, g_rspart); float*  Rpp = (float*)p;

    cudaFuncSetAttribute(qkv_proj_kernel,
        cudaFuncAttributeMaxDynamicSharedMemorySize, PJ_SMEM_BYTES);
    cudaFuncSetAttribute(out_proj_kernel,
        cudaFuncAttributeMaxDynamicSharedMemorySize, PJ_SMEM_BYTES);

    // QKV projections
    qkv_proj_kernel<<<dim3(12, SEQ / 128), 256, PJ_SMEM_BYTES>>>(
        x, Wq, bq, Wk, bk, Wv, bv, Qp, Kp, Vp);

    // preps (pair-interleaved layouts)
    k2h_kernel<<<(SEQ * HKV * HD) / 4 / 256, 256>>>(Kp, Khp);
    vt_kernel<<<dim3(SEQ / 32, HD / 32, HKV), dim3(32, 8)>>>(Vp, Vtp);

    // Pass 1: partial rowsums (64-key tiles, 4-way key split, high occupancy)
    rowsum_kernel<<<dim3(SEQ / 64, HQ, RSPLIT), 128>>>(Qp, Khp, Rpp);

    // Pass 2: fused scores + softmax write + PV (cp.async pipeline)
    fused_att_kernel<<<dim3(SEQ / 64, HQ), 128>>>(Qp, Khp, Vtp, Rpp, att, Cp);

    // out = ctx @ Wo + bo
    out_proj_kernel<<<dim3(DIMX / 64, SEQ / 128), 256, PJ_SMEM_BYTES>>>(
        Cp, Wo, bo, out);
}

// round 14
// speedup vs baseline: 1.2711x; 1.1391x over previous
#include <cuda_runtime.h>
#include <cuda_fp16.h>
#include <cstdint>

// Problem constants
#define DIMX 768
#define HQ   8
#define HKV  2
#define HD   64
#define SEQ  4096
#define NREP (HQ / HKV)   // 4
#define RSPLIT 4          // rowsum key split
#define DQ   (HQ * HD)    // 512
#define DKV  (HKV * HD)   // 128

// Scratch (allocation-free rule: __device__ globals) — all half, pair-interleaved
__device__ __half g_xh[SEQ * DIMX];          // x, interleaved k
__device__ __half g_Wtq[DQ * DIMX];          // Wq^T [512][768], interleaved k, xQSCALE
__device__ __half g_Wtk[DKV * DIMX];         // Wk^T [128][768]
__device__ __half g_Wtv[DKV * DIMX];         // Wv^T [128][768]
__device__ __half g_Wto[DIMX * DQ];          // Wo^T [768][512]
__device__ __half g_Qh[SEQ * DQ];            // Q (pre-scaled), interleaved
__device__ __half g_Kh[SEQ * DKV];           // K, interleaved
__device__ __half g_Vh[SEQ * DKV];           // V, interleaved
__device__ __half g_Vt[HKV * HD * SEQ];      // V^T [2][64][4096], s interleaved
__device__ __half g_Ch[SEQ * DQ];            // context, interleaved
__device__ float  g_rspart[RSPLIT * HQ * SEQ];

// ===========================================================================
// helpers
// ===========================================================================
__device__ __forceinline__ void mma_f16(float* c, const uint32_t* a, uint32_t b0, uint32_t b1) {
    asm volatile(
        "mma.sync.aligned.m16n8k16.row.col.f32.f16.f16.f32 "
        "{%0,%1,%2,%3}, {%4,%5,%6,%7}, {%8,%9}, {%0,%1,%2,%3};"
        : "+f"(c[0]), "+f"(c[1]), "+f"(c[2]), "+f"(c[3])
        : "r"(a[0]), "r"(a[1]), "r"(a[2]), "r"(a[3]), "r"(b0), "r"(b1));
}
__device__ __forceinline__ uint32_t pack2(float a, float b) {
    __half2 h = __floats2half2_rn(a, b);
    return *reinterpret_cast<uint32_t*>(&h);
}
__device__ __forceinline__ float ex2(float x) {
    float y;
    asm("ex2.approx.f32 %0, %1;" : "=f"(y) : "f"(x));
    return y;
}
__device__ __forceinline__ float2 ex2h2(float a, float b) {
    uint32_t in = pack2(a, b);
    uint32_t out;
    asm("ex2.approx.f16x2 %0, %1;" : "=r"(out) : "r"(in));
    __half2 h = *reinterpret_cast<__half2*>(&out);
    return __half22float2(h);
}
__device__ __forceinline__ void stg_cs_v2(float* p, float a, float b) {
    asm volatile("st.global.cs.v2.f32 [%0], {%1, %2};"
                 :: "l"(p), "f"(a), "f"(b) : "memory");
}
// cp.async helpers
__device__ __forceinline__ void cp16(__half* sdst, const __half* gsrc) {
    uint32_t s;
    asm("{ .reg .u64 a; cvta.to.shared.u64 a, %1; cvt.u32.u64 %0, a; }"
        : "=r"(s) : "l"(sdst));
    asm volatile("cp.async.cg.shared.global [%0], [%1], 16;"
                 :: "r"(s), "l"(gsrc) : "memory");
}
#define CPASYNC_COMMIT() asm volatile("cp.async.commit_group;" ::: "memory")
#define CPASYNC_WAIT1()  asm volatile("cp.async.wait_group 1;" ::: "memory")
#define CPASYNC_WAIT0()  asm volatile("cp.async.wait_group 0;" ::: "memory")

// pair-interleave maps (within 16-element groups): {2u,2u+1,2u+8,2u+9} -> 4u..4u+3
__device__ __forceinline__ int perm16(int s) {
    int q = s & 15;
    int p = (q < 8) ? ((q >> 1) * 4 + (q & 1))
                    : (((q - 8) >> 1) * 4 + 2 + (q & 1));
    return (s & ~15) | p;
}
// position of even natural col c (pair c,c+1) in interleaved storage
__device__ __forceinline__ int ipos(int c) {
    int off = c & 15;
    int stored = (off < 8) ? (2 * off) : (2 * (off - 8) + 2);
    return (c & ~15) | stored;
}

#define QSCALE 0.1803368801111204f   // 1/sqrt(64) * log2(e)
#define HPAD 80                      // half tile row stride

// ===========================================================================
// Prep: fp32 -> half, pair-interleaved (flat, len multiple of 1024)
// ===========================================================================
__global__ void f2h_kernel(const float* __restrict__ src, __half* __restrict__ dst)
{
    int i = blockIdx.x * 256 + threadIdx.x;   // uint2 index (4 halves)
    int u = i & 3;
    int chunk = i >> 2;
    const float* s = src + (size_t)chunk * 16 + 2 * u;
    float2 lo = *(const float2*)s;
    float2 hi = *(const float2*)(s + 8);
    uint2 o;
    o.x = pack2(lo.x, lo.y);
    o.y = pack2(hi.x, hi.y);
    *(uint2*)((char*)dst + (size_t)i * 8) = o;
}

// ===========================================================================
// Prep: W[K][N] fp32 -> Wt[N][K] half, K pair-interleaved, scaled.
// ===========================================================================
__global__ void wt_kernel(const float* __restrict__ W, __half* __restrict__ Wt,
                          int K, int N, float scale)
{
    __shared__ float tile[32][33];
    const int k0 = blockIdx.x * 32, n0 = blockIdx.y * 32;
    const int tx = threadIdx.x, ty = threadIdx.y;
#pragma unroll
    for (int i = 0; i < 32; i += 8)
        tile[ty + i][tx] = W[(size_t)(k0 + ty + i) * N + n0 + tx];
    __syncthreads();
#pragma unroll
    for (int i = 0; i < 32; i += 8)
        Wt[(size_t)(n0 + ty + i) * K + (k0 & ~31) + perm16(k0 % 32 + tx)] =
            __float2half_rn(tile[tx][ty + i] * scale);
}

// ===========================================================================
// Prep: Vh [s][128] (interleaved d) -> Vt [kh][d][s] (interleaved s)
// ===========================================================================
__global__ void vt_kernel(const __half* __restrict__ Vh, __half* __restrict__ Vt)
{
    __shared__ __half tile[32][33];
    const int kh = blockIdx.z;
    const int s0 = blockIdx.x * 32;
    const int d0 = blockIdx.y * 32;
    const int tx = threadIdx.x, ty = threadIdx.y;
#pragma unroll
    for (int i = 0; i < 32; i += 8)
        tile[ty + i][tx] = Vh[(size_t)(s0 + ty + i) * DKV + kh * HD + perm16(d0 + tx)];
    __syncthreads();
#pragma unroll
    for (int i = 0; i < 32; i += 8)
        Vt[(size_t)kh * HD * SEQ + (size_t)(d0 + ty + i) * SEQ + s0 + perm16(tx)] =
            tile[tx][ty + i];
}

// ===========================================================================
// Q fragment loader: direct LDG.64 from interleaved half Q (pre-scaled)
// ===========================================================================
__device__ __forceinline__ void load_qfrag(
    uint32_t qf[4][4], const __half* __restrict__ Qh,
    int row0, int h, int g, int t4)
{
    const __half* q0 = Qh + (size_t)(row0 + g) * DQ + h * HD;
    const __half* q1 = q0 + (size_t)8 * DQ;
#pragma unroll
    for (int ks = 0; ks < 4; ks++) {
        uint2 lo = *(const uint2*)(q0 + ks * 16 + t4 * 4);
        uint2 hi = *(const uint2*)(q1 + ks * 16 + t4 * 4);
        qf[ks][0] = lo.x; qf[ks][1] = hi.x; qf[ks][2] = lo.y; qf[ks][3] = hi.y;
    }
}

// B-fragment: one LDS.64 from pair-interleaved storage
__device__ __forceinline__ uint2 bfrag(const __half* base, int n, int ks, int t4) {
    return *(const uint2*)(base + n * HPAD + ks * 16 + t4 * 4);
}

// ===========================================================================
// fp16 projection mainloop: acc[2][4][4] += A[m0..+128, :] @ Bt[n0..+64, :]^T
// 256 thr, warps 4(m) x 2(n), 32 rows x 32 cols per warp. cp.async pipeline.
// ===========================================================================
#define PROJH_SMEM ((2 * 128 * HPAD + 2 * 64 * HPAD) * 2)

__device__ __forceinline__ void projh_loop(
    const __half* __restrict__ A, int lda,
    const __half* __restrict__ Bt, int ldb, int Kdim,
    int m0, int n0, float acc[2][4][4])
{
    extern __shared__ __half smh[];
    __half* As0 = smh;                       // [2][128*HPAD]
    __half* Bs0 = smh + 2 * 128 * HPAD;      // [2][64*HPAD]

    const int t = threadIdx.x, lane = t & 31, wid = t >> 5;
    const int wm = wid >> 1, wn = wid & 1;
    const int g = lane >> 2, t4 = lane & 3;

    // first tile
    {
#pragma unroll
        for (int i = 0; i < 4; i++) {
            int e = t + i * 256;
            int r = e >> 3, seg = e & 7;
            cp16(&As0[r * HPAD + seg * 8], A + (size_t)(m0 + r) * lda + seg * 8);
        }
#pragma unroll
        for (int i = 0; i < 2; i++) {
            int e = t + i * 256;
            int r = e >> 3, seg = e & 7;
            cp16(&Bs0[r * HPAD + seg * 8], Bt + (size_t)(n0 + r) * ldb + seg * 8);
        }
        CPASYNC_COMMIT();
    }

    const int nk = Kdim / 64;
    for (int kt = 0; kt < nk; kt++) {
        const int buf = kt & 1;
        __syncthreads();
        if (kt + 1 < nk) {
            const int k0n = (kt + 1) * 64;
            __half* Ad = As0 + (buf ^ 1) * 128 * HPAD;
            __half* Bd = Bs0 + (buf ^ 1) * 64 * HPAD;
#pragma unroll
            for (int i = 0; i < 4; i++) {
                int e = t + i * 256;
                int r = e >> 3, seg = e & 7;
                cp16(&Ad[r * HPAD + seg * 8], A + (size_t)(m0 + r) * lda + k0n + seg * 8);
            }
#pragma unroll
            for (int i = 0; i < 2; i++) {
                int e = t + i * 256;
                int r = e >> 3, seg = e & 7;
                cp16(&Bd[r * HPAD + seg * 8], Bt + (size_t)(n0 + r) * ldb + k0n + seg * 8);
            }
            CPASYNC_COMMIT();
            CPASYNC_WAIT1();
        } else {
            CPASYNC_WAIT0();
        }
        __syncthreads();

        const __half* As = As0 + buf * 128 * HPAD;
        const __half* Bs = Bs0 + buf * 64 * HPAD;
#pragma unroll
        for (int ks = 0; ks < 4; ks++) {
            uint32_t Af[2][4];
#pragma unroll
            for (int rg = 0; rg < 2; rg++) {
                int rr = wm * 32 + rg * 16;
                uint2 lo = *(const uint2*)&As[(rr + g) * HPAD + ks * 16 + t4 * 4];
                uint2 hi = *(const uint2*)&As[(rr + 8 + g) * HPAD + ks * 16 + t4 * 4];
                Af[rg][0] = lo.x; Af[rg][1] = hi.x; Af[rg][2] = lo.y; Af[rg][3] = hi.y;
            }
#pragma unroll
            for (int j = 0; j < 4; j++) {
                uint2 b = *(const uint2*)&Bs[(wn * 32 + j * 8 + g) * HPAD + ks * 16 + t4 * 4];
                mma_f16(acc[0][j], Af[0], b.x, b.y);
                mma_f16(acc[1][j], Af[1], b.x, b.y);
            }
        }
    }
}

// QKV projection: output half, pair-interleaved. grid (12, SEQ/128).
__global__ __launch_bounds__(256, 3) void qkv_projh_kernel(
    const __half* __restrict__ xh,
    const __half* __restrict__ Wtq, const float* __restrict__ bq,
    const __half* __restrict__ Wtk, const float* __restrict__ bk,
    const __half* __restrict__ Wtv, const float* __restrict__ bv,
    __half* __restrict__ Qo, __half* __restrict__ Ko, __half* __restrict__ Vo)
{
    const int seg = blockIdx.x;
    const int m0 = blockIdx.y * 128;
    const __half* Bt; const float* bias; __half* C;
    int ldc, n0; float bscale = 1.f;
    if (seg < 8)       { Bt = Wtq; bias = bq; C = Qo; ldc = DQ;  n0 = seg * 64; bscale = QSCALE; }
    else if (seg < 10) { Bt = Wtk; bias = bk; C = Ko; ldc = DKV; n0 = (seg - 8) * 64; }
    else               { Bt = Wtv; bias = bv; C = Vo; ldc = DKV; n0 = (seg - 10) * 64; }

    float acc[2][4][4];
#pragma unroll
    for (int i = 0; i < 2; i++)
#pragma unroll
        for (int j = 0; j < 4; j++)
#pragma unroll
            for (int c = 0; c < 4; c++) acc[i][j][c] = 0.f;

    projh_loop(xh, DIMX, Bt, DIMX, DIMX, m0, n0, acc);

    const int lane = threadIdx.x & 31, wid = threadIdx.x >> 5;
    const int wm = wid >> 1, wn = wid & 1, g = lane >> 2, t4 = lane & 3;
#pragma unroll
    for (int rg = 0; rg < 2; rg++) {
        int r0 = m0 + wm * 32 + rg * 16 + g;
#pragma unroll
        for (int j = 0; j < 4; j++) {
            int c = n0 + wn * 32 + j * 8 + t4 * 2;
            float b0 = bias[c] * bscale, b1 = bias[c + 1] * bscale;
            int pos = ipos(c);
            *(uint32_t*)(C + (size_t)r0 * ldc + pos) =
                pack2(acc[rg][j][0] + b0, acc[rg][j][1] + b1);
            *(uint32_t*)(C + (size_t)(r0 + 8) * ldc + pos) =
                pack2(acc[rg][j][2] + b0, acc[rg][j][3] + b1);
        }
    }
}

// Output projection: fp32 natural output. grid (DIMX/64, SEQ/128).
__global__ __launch_bounds__(256, 3) void out_projh_kernel(
    const __half* __restrict__ Ch, const __half* __restrict__ Wto,
    const float* __restrict__ bo, float* __restrict__ out)
{
    const int n0 = blockIdx.x * 64;
    const int m0 = blockIdx.y * 128;

    float acc[2][4][4];
#pragma unroll
    for (int i = 0; i < 2; i++)
#pragma unroll
        for (int j = 0; j < 4; j++)
#pragma unroll
            for (int c = 0; c < 4; c++) acc[i][j][c] = 0.f;

    projh_loop(Ch, DQ, Wto, DQ, DQ, m0, n0, acc);

    const int lane = threadIdx.x & 31, wid = threadIdx.x >> 5;
    const int wm = wid >> 1, wn = wid & 1, g = lane >> 2, t4 = lane & 3;
#pragma unroll
    for (int rg = 0; rg < 2; rg++) {
        int r0 = m0 + wm * 32 + rg * 16 + g;
#pragma unroll
        for (int j = 0; j < 4; j++) {
            int col = n0 + wn * 32 + j * 8 + t4 * 2;
            float b0 = bo[col], b1 = bo[col + 1];
            *(float2*)(out + (size_t)r0 * DIMX + col) =
                make_float2(acc[rg][j][0] + b0, acc[rg][j][1] + b1);
            *(float2*)(out + (size_t)(r0 + 8) * DIMX + col) =
                make_float2(acc[rg][j][2] + b0, acc[rg][j][3] + b1);
        }
    }
}

// ===========================================================================
// Pass 1: partial rowsums. 128 thr, 4 warps x 32 rows = 128-row tile.
// grid (SEQ/128, HQ, RSPLIT). 64-key tiles, cp.async, B-frag reuse x2.
// ===========================================================================
__global__ __launch_bounds__(128, 6) void rowsum_kernel(
    const __half* __restrict__ Qh, const __half* __restrict__ Kh,
    float* __restrict__ rspart)
{
    __shared__ __half Ks[2][64 * HPAD];

    const int t = threadIdx.x, lane = t & 31, wid = t >> 5;
    const int g = lane >> 2, t4 = lane & 3;
    const int m0 = blockIdx.x * 128, h = blockIdx.y, sp = blockIdx.z;
    const int kh = h / NREP;

    uint32_t qfA[4][4], qfB[4][4];
    load_qfrag(qfA, Qh, m0 + wid * 32, h, g, t4);
    load_qfrag(qfB, Qh, m0 + wid * 32 + 16, h, g, t4);

    float rs[4] = {0.f, 0.f, 0.f, 0.f};
    const int it0 = sp * (SEQ / 64 / RSPLIT);
    const int it1 = it0 + (SEQ / 64 / RSPLIT);

    {
        const int n0 = it0 * 64;
#pragma unroll
        for (int i = 0; i < 4; i++) {
            int e = t + i * 128;
            int r = e >> 3, seg = e & 7;
            cp16(&Ks[0][r * HPAD + seg * 8],
                 Kh + (size_t)(n0 + r) * DKV + kh * HD + seg * 8);
        }
        CPASYNC_COMMIT();
    }

    for (int it = it0; it < it1; it++) {
        const int buf = (it - it0) & 1;
        __syncthreads();
        if (it + 1 < it1) {
            const int n0 = (it + 1) * 64;
#pragma unroll
            for (int i = 0; i < 4; i++) {
                int e = t + i * 128;
                int r = e >> 3, seg = e & 7;
                cp16(&Ks[buf ^ 1][r * HPAD + seg * 8],
                     Kh + (size_t)(n0 + r) * DKV + kh * HD + seg * 8);
            }
            CPASYNC_COMMIT();
            CPASYNC_WAIT1();
        } else {
            CPASYNC_WAIT0();
        }
        __syncthreads();

        const __half* kb = Ks[buf];
#pragma unroll
        for (int j = 0; j < 8; j++) {
            float sA[4] = {0.f, 0.f, 0.f, 0.f};
            float sB[4] = {0.f, 0.f, 0.f, 0.f};
#pragma unroll
            for (int ks = 0; ks < 4; ks++) {
                uint2 b = bfrag(kb, j * 8 + g, ks, t4);
                mma_f16(sA, qfA[ks], b.x, b.y);
                mma_f16(sB, qfB[ks], b.x, b.y);
            }
            float2 e0 = ex2h2(sA[0], sA[1]);
            float2 e1 = ex2h2(sA[2], sA[3]);
            float2 e2 = ex2h2(sB[0], sB[1]);
            float2 e3 = ex2h2(sB[2], sB[3]);
            rs[0] += e0.x + e0.y;
            rs[1] += e1.x + e1.y;
            rs[2] += e2.x + e2.y;
            rs[3] += e3.x + e3.y;
        }
    }

#pragma unroll
    for (int i = 0; i < 4; i++) {
        rs[i] += __shfl_xor_sync(0xffffffffu, rs[i], 1);
        rs[i] += __shfl_xor_sync(0xffffffffu, rs[i], 2);
    }
    if (t4 == 0) {
        float* dst = rspart + (size_t)sp * HQ * SEQ + (size_t)h * SEQ + m0 + wid * 32;
        dst[g]      = rs[0];
        dst[g + 8]  = rs[1];
        dst[g + 16] = rs[2];
        dst[g + 24] = rs[3];
    }
}

// ===========================================================================
// Pass 2: fused scores + softmax write (.cs) + PV. 128 thr, 4 warps x 16 rows.
// grid (SEQ/64, HQ). cp.async double buffer. ctx stored half interleaved.
// ===========================================================================
__global__ __launch_bounds__(128) void fused_att_kernel(
    const __half* __restrict__ Qh, const __half* __restrict__ Kh,
    const __half* __restrict__ Vt, const float* __restrict__ rspart,
    float* __restrict__ att, __half* __restrict__ Ch)
{
    __shared__ __half Ks[2][64 * HPAD];
    __shared__ __half Vs[2][64 * HPAD];
    __shared__ float sinv[64];

    const int t = threadIdx.x, lane = t & 31, wid = t >> 5;
    const int g = lane >> 2, t4 = lane & 3;
    const int m0 = blockIdx.x * 64, h = blockIdx.y;
    const int kh = h / NREP;

    if (t < 64) {
        const float* rp = rspart + (size_t)h * SEQ + m0 + t;
        float s = rp[0];
#pragma unroll
        for (int i = 1; i < RSPLIT; i++) s += rp[(size_t)i * HQ * SEQ];
        sinv[t] = 1.0f / s;
    }

    uint32_t qf[4][4];
    load_qfrag(qf, Qh, m0 + wid * 16, h, g, t4);

    const __half* vth = Vt + (size_t)kh * HD * SEQ;

    {
#pragma unroll
        for (int i = 0; i < 4; i++) {
            int e = t + i * 128;
            int r = e >> 3, seg = e & 7;
            cp16(&Ks[0][r * HPAD + seg * 8],
                 Kh + (size_t)r * DKV + kh * HD + seg * 8);
            cp16(&Vs[0][r * HPAD + seg * 8],
                 vth + (size_t)r * SEQ + seg * 8);
        }
        CPASYNC_COMMIT();
    }
    __syncthreads();   // sinv visible

    const int rl = wid * 16 + g;
    const float inv_lo = sinv[rl];
    const float inv_hi = sinv[rl + 8];

    float ctx[8][4];
#pragma unroll
    for (int j = 0; j < 8; j++)
#pragma unroll
        for (int c = 0; c < 4; c++) ctx[j][c] = 0.f;

    float* atth = att + (size_t)h * SEQ * SEQ;

    for (int it = 0; it < SEQ / 64; it++) {
        const int buf = it & 1;
        __syncthreads();
        if (it + 1 < SEQ / 64) {
            const int k0n = (it + 1) * 64;
#pragma unroll
            for (int i = 0; i < 4; i++) {
                int e = t + i * 128;
                int r = e >> 3, seg = e & 7;
                cp16(&Ks[buf ^ 1][r * HPAD + seg * 8],
                     Kh + (size_t)(k0n + r) * DKV + kh * HD + seg * 8);
                cp16(&Vs[buf ^ 1][r * HPAD + seg * 8],
                     vth + (size_t)r * SEQ + k0n + seg * 8);
            }
            CPASYNC_COMMIT();
            CPASYNC_WAIT1();
        } else {
            CPASYNC_WAIT0();
        }
        __syncthreads();

        const __half* kb = Ks[buf];
        const __half* vb = Vs[buf];
        const int k0 = it * 64;

        float sacc[8][4];
#pragma unroll
        for (int j = 0; j < 8; j++)
#pragma unroll
            for (int c = 0; c < 4; c++) sacc[j][c] = 0.f;

#pragma unroll
        for (int ks = 0; ks < 4; ks++) {
#pragma unroll
            for (int j = 0; j < 8; j++) {
                uint2 b = bfrag(kb, j * 8 + g, ks, t4);
                mma_f16(sacc[j], qf[ks], b.x, b.y);
            }
        }

        const size_t rowbase = (size_t)(m0 + rl) * SEQ + k0;
        uint32_t pk[8][2];
#pragma unroll
        for (int j = 0; j < 8; j++) {
            float p0 = ex2(sacc[j][0]) * inv_lo;
            float p1 = ex2(sacc[j][1]) * inv_lo;
            float p2 = ex2(sacc[j][2]) * inv_hi;
            float p3 = ex2(sacc[j][3]) * inv_hi;
            int cj = j * 8 + t4 * 2;
            stg_cs_v2(atth + rowbase + cj, p0, p1);
            stg_cs_v2(atth + rowbase + 8 * SEQ + cj, p2, p3);
            pk[j][0] = pack2(p0, p1);
            pk[j][1] = pack2(p2, p3);
        }

#pragma unroll
        for (int kc = 0; kc < 4; kc++) {
            uint32_t A[4] = { pk[2 * kc][0], pk[2 * kc][1],
                              pk[2 * kc + 1][0], pk[2 * kc + 1][1] };
#pragma unroll
            for (int jj = 0; jj < 8; jj++) {
                uint2 b = bfrag(vb, jj * 8 + g, kc, t4);
                mma_f16(ctx[jj], A, b.x, b.y);
            }
        }
    }

    // store context (half, pair-interleaved)
#pragma unroll
    for (int jj = 0; jj < 8; jj++) {
        int c = h * HD + jj * 8 + t4 * 2;
        int pos = ipos(c);
        *(uint32_t*)(Ch + (size_t)(m0 + rl) * DQ + pos) = pack2(ctx[jj][0], ctx[jj][1]);
        *(uint32_t*)(Ch + (size_t)(m0 + rl + 8) * DQ + pos) = pack2(ctx[jj][2], ctx[jj][3]);
    }
}

// ===========================================================================
extern "C" void kernel_launch(void* const* d_in, const int* in_sizes, int n_in,
                              void* d_out, int out_size)
{
    const float* x  = (const float*)d_in[0];
    const float* Wq = (const float*)d_in[1];
    const float* bq = (const float*)d_in[2];
    const float* Wk = (const float*)d_in[3];
    const float* bk = (const float*)d_in[4];
    const float* Wv = (const float*)d_in[5];
    const float* bv = (const float*)d_in[6];
    const float* Wo = (const float*)d_in[7];
    const float* bo = (const float*)d_in[8];

    float* out = (float*)d_out;                 // [4096, 768]
    float* att = out + (size_t)SEQ * DIMX;      // [8, 4096, 4096]

    void* p;
    cudaGetSymbolAddress(&p, g_xh);     __half* xhp  = (__half*)p;
    cudaGetSymbolAddress(&p, g_Wtq);    __half* Wtqp = (__half*)p;
    cudaGetSymbolAddress(&p, g_Wtk);    __half* Wtkp = (__half*)p;
    cudaGetSymbolAddress(&p, g_Wtv);    __half* Wtvp = (__half*)p;
    cudaGetSymbolAddress(&p, g_Wto);    __half* Wtop = (__half*)p;
    cudaGetSymbolAddress(&p, g_Qh);     __half* Qhp  = (__half*)p;
    cudaGetSymbolAddress(&p, g_Kh);     __half* Khp  = (__half*)p;
    cudaGetSymbolAddress(&p, g_Vh);     __half* Vhp  = (__half*)p;
    cudaGetSymbolAddress(&p, g_Vt);     __half* Vtp  = (__half*)p;
    cudaGetSymbolAddress(&p, g_Ch);     __half* Chp  = (__half*)p;
    cudaGetSymbolAddress(&p, g_rspart); float*  Rpp  = (float*)p;

    cudaFuncSetAttribute(qkv_projh_kernel,
        cudaFuncAttributeMaxDynamicSharedMemorySize, PROJH_SMEM);
    cudaFuncSetAttribute(out_projh_kernel,
        cudaFuncAttributeMaxDynamicSharedMemorySize, PROJH_SMEM);

    // preps: x and weights to half (interleaved); Wq/bq pre-scaled by QSCALE
    f2h_kernel<<<(SEQ * DIMX) / 1024, 256>>>(x, xhp);
    wt_kernel<<<dim3(DIMX / 32, DQ / 32),  dim3(32, 8)>>>(Wq, Wtqp, DIMX, DQ,  QSCALE);
    wt_kernel<<<dim3(DIMX / 32, DKV / 32), dim3(32, 8)>>>(Wk, Wtkp, DIMX, DKV, 1.f);
    wt_kernel<<<dim3(DIMX / 32, DKV / 32), dim3(32, 8)>>>(Wv, Wtvp, DIMX, DKV, 1.f);
    wt_kernel<<<dim3(DQ / 32, DIMX / 32),  dim3(32, 8)>>>(Wo, Wtop, DQ, DIMX, 1.f);

    // QKV projections (fp16 mma)
    qkv_projh_kernel<<<dim3(12, SEQ / 128), 256, PROJH_SMEM>>>(
        xhp, Wtqp, bq, Wtkp, bk, Wtvp, bv, Qhp, Khp, Vhp);

    // V transpose
    vt_kernel<<<dim3(SEQ / 32, HD / 32, HKV), dim3(32, 8)>>>(Vhp, Vtp);

    // Pass 1: partial rowsums
    rowsum_kernel<<<dim3(SEQ / 128, HQ, RSPLIT), 128>>>(Qhp, Khp, Rpp);

    // Pass 2: fused scores + softmax write + PV
    fused_att_kernel<<<dim3(SEQ / 64, HQ), 128>>>(Qhp, Khp, Vtp, Rpp, att, Chp);

    // out = ctx @ Wo + bo (fp16 mma)
    out_projh_kernel<<<dim3(DIMX / 64, SEQ / 128), 256, PROJH_SMEM>>>(
        Chp, Wtop, bo, out);
}

// round 16
// speedup vs baseline: 1.2835x; 1.0097x over previous
#include <cuda_runtime.h>
#include <cuda_fp16.h>
#include <cstdint>

// Problem constants
#define DIMX 768
#define HQ   8
#define HKV  2
#define HD   64
#define SEQ  4096
#define NREP (HQ / HKV)   // 4
#define RSPLIT 8          // rowsum key split
#define DQ   (HQ * HD)    // 512
#define DKV  (HKV * HD)   // 128

// Scratch (allocation-free rule: __device__ globals) — all half, pair-interleaved
__device__ __half g_xh[SEQ * DIMX];          // x, interleaved k
__device__ __half g_Wtq[DQ * DIMX];          // Wq^T [512][768], interleaved k, xQSCALE
__device__ __half g_Wtk[DKV * DIMX];         // Wk^T [128][768]
__device__ __half g_Wtv[DKV * DIMX];         // Wv^T [128][768]
__device__ __half g_Wto[DIMX * DQ];          // Wo^T [768][512]
__device__ __half g_Qh[SEQ * DQ];            // Q (pre-scaled), interleaved
__device__ __half g_Kh[SEQ * DKV];           // K, interleaved
__device__ __half g_Vh[SEQ * DKV];           // V, interleaved
__device__ __half g_Vt[HKV * HD * SEQ];      // V^T [2][64][4096], s interleaved
__device__ __half g_Ch[SEQ * DQ];            // context, interleaved
__device__ float  g_rspart[RSPLIT * HQ * SEQ];

// ===========================================================================
// helpers
// ===========================================================================
__device__ __forceinline__ void mma_f16(float* c, const uint32_t* a, uint32_t b0, uint32_t b1) {
    asm volatile(
        "mma.sync.aligned.m16n8k16.row.col.f32.f16.f16.f32 "
        "{%0,%1,%2,%3}, {%4,%5,%6,%7}, {%8,%9}, {%0,%1,%2,%3};"
        : "+f"(c[0]), "+f"(c[1]), "+f"(c[2]), "+f"(c[3])
        : "r"(a[0]), "r"(a[1]), "r"(a[2]), "r"(a[3]), "r"(b0), "r"(b1));
}
__device__ __forceinline__ uint32_t pack2(float a, float b) {
    __half2 h = __floats2half2_rn(a, b);
    return *reinterpret_cast<uint32_t*>(&h);
}
__device__ __forceinline__ float ex2(float x) {
    float y;
    asm("ex2.approx.f32 %0, %1;" : "=f"(y) : "f"(x));
    return y;
}
__device__ __forceinline__ float2 ex2h2(float a, float b) {
    uint32_t in = pack2(a, b);
    uint32_t out;
    asm("ex2.approx.f16x2 %0, %1;" : "=r"(out) : "r"(in));
    __half2 h = *reinterpret_cast<__half2*>(&out);
    return __half22float2(h);
}
__device__ __forceinline__ void stg_cs_v2(float* p, float a, float b) {
    asm volatile("st.global.cs.v2.f32 [%0], {%1, %2};"
                 :: "l"(p), "f"(a), "f"(b) : "memory");
}
// cp.async helpers
__device__ __forceinline__ void cp16(__half* sdst, const __half* gsrc) {
    uint32_t s;
    asm("{ .reg .u64 a; cvta.to.shared.u64 a, %1; cvt.u32.u64 %0, a; }"
        : "=r"(s) : "l"(sdst));
    asm volatile("cp.async.cg.shared.global [%0], [%1], 16;"
                 :: "r"(s), "l"(gsrc) : "memory");
}
#define CPASYNC_COMMIT() asm volatile("cp.async.commit_group;" ::: "memory")
#define CPASYNC_WAIT1()  asm volatile("cp.async.wait_group 1;" ::: "memory")
#define CPASYNC_WAIT0()  asm volatile("cp.async.wait_group 0;" ::: "memory")

// pair-interleave maps (within 16-element groups)
__device__ __forceinline__ int perm16(int s) {
    int q = s & 15;
    int p = (q < 8) ? ((q >> 1) * 4 + (q & 1))
                    : (((q - 8) >> 1) * 4 + 2 + (q & 1));
    return (s & ~15) | p;
}
__device__ __forceinline__ int ipos(int c) {
    int off = c & 15;
    int stored = (off < 8) ? (2 * off) : (2 * (off - 8) + 2);
    return (c & ~15) | stored;
}

#define QSCALE 0.1803368801111204f   // 1/sqrt(64) * log2(e)
#define HPAD 80                      // half tile row stride

// ===========================================================================
// Prep: fp32 -> half, pair-interleaved (flat)
// ===========================================================================
__global__ void f2h_kernel(const float* __restrict__ src, __half* __restrict__ dst)
{
    int i = blockIdx.x * 256 + threadIdx.x;
    int u = i & 3;
    int chunk = i >> 2;
    const float* s = src + (size_t)chunk * 16 + 2 * u;
    float2 lo = *(const float2*)s;
    float2 hi = *(const float2*)(s + 8);
    uint2 o;
    o.x = pack2(lo.x, lo.y);
    o.y = pack2(hi.x, hi.y);
    *(uint2*)((char*)dst + (size_t)i * 8) = o;
}

// ===========================================================================
// Prep: ALL FOUR weight transposes in one kernel.
// blockIdx.z selects the weight. W[K][N] fp32 -> Wt[N][K] half interleaved.
// Grid (24, 24, 4) covers the largest K AND N; out-of-range tiles early-out.
// ===========================================================================
__global__ void wt4_kernel(
    const float* __restrict__ Wq, const float* __restrict__ Wk,
    const float* __restrict__ Wv, const float* __restrict__ Wo,
    __half* __restrict__ Wtq, __half* __restrict__ Wtk,
    __half* __restrict__ Wtv, __half* __restrict__ Wto)
{
    __shared__ float tile[32][33];
    const int which = blockIdx.z;
    const float* W;
    __half* Wt;
    int K, N;
    float scale = 1.f;
    if (which == 0)      { W = Wq; Wt = Wtq; K = DIMX; N = DQ;  scale = QSCALE; }
    else if (which == 1) { W = Wk; Wt = Wtk; K = DIMX; N = DKV; }
    else if (which == 2) { W = Wv; Wt = Wtv; K = DIMX; N = DKV; }
    else                 { W = Wo; Wt = Wto; K = DQ;   N = DIMX; }

    const int k0 = blockIdx.x * 32, n0 = blockIdx.y * 32;
    if (k0 >= K || n0 >= N) return;
    const int tx = threadIdx.x, ty = threadIdx.y;
#pragma unroll
    for (int i = 0; i < 32; i += 8)
        tile[ty + i][tx] = W[(size_t)(k0 + ty + i) * N + n0 + tx];
    __syncthreads();
#pragma unroll
    for (int i = 0; i < 32; i += 8)
        Wt[(size_t)(n0 + ty + i) * K + (k0 & ~31) + perm16(k0 % 32 + tx)] =
            __float2half_rn(tile[tx][ty + i] * scale);
}

// ===========================================================================
// Prep: Vh [s][128] (interleaved d) -> Vt [kh][d][s] (interleaved s)
// ===========================================================================
__global__ void vt_kernel(const __half* __restrict__ Vh, __half* __restrict__ Vt)
{
    __shared__ __half tile[32][33];
    const int kh = blockIdx.z;
    const int s0 = blockIdx.x * 32;
    const int d0 = blockIdx.y * 32;
    const int tx = threadIdx.x, ty = threadIdx.y;
#pragma unroll
    for (int i = 0; i < 32; i += 8)
        tile[ty + i][tx] = Vh[(size_t)(s0 + ty + i) * DKV + kh * HD + perm16(d0 + tx)];
    __syncthreads();
#pragma unroll
    for (int i = 0; i < 32; i += 8)
        Vt[(size_t)kh * HD * SEQ + (size_t)(d0 + ty + i) * SEQ + s0 + perm16(tx)] =
            tile[tx][ty + i];
}

// ===========================================================================
// Q fragment loader: direct LDG.64 from interleaved half Q (pre-scaled)
// ===========================================================================
__device__ __forceinline__ void load_qfrag(
    uint32_t qf[4][4], const __half* __restrict__ Qh,
    int row0, int h, int g, int t4)
{
    const __half* q0 = Qh + (size_t)(row0 + g) * DQ + h * HD;
    const __half* q1 = q0 + (size_t)8 * DQ;
#pragma unroll
    for (int ks = 0; ks < 4; ks++) {
        uint2 lo = *(const uint2*)(q0 + ks * 16 + t4 * 4);
        uint2 hi = *(const uint2*)(q1 + ks * 16 + t4 * 4);
        qf[ks][0] = lo.x; qf[ks][1] = hi.x; qf[ks][2] = lo.y; qf[ks][3] = hi.y;
    }
}

__device__ __forceinline__ uint2 bfrag(const __half* base, int n, int ks, int t4) {
    return *(const uint2*)(base + n * HPAD + ks * 16 + t4 * 4);
}

// ===========================================================================
// fp16 projection mainloop (cp.async pipeline)
// ===========================================================================
#define PROJH_SMEM ((2 * 128 * HPAD + 2 * 64 * HPAD) * 2)

__device__ __forceinline__ void projh_loop(
    const __half* __restrict__ A, int lda,
    const __half* __restrict__ Bt, int ldb, int Kdim,
    int m0, int n0, float acc[2][4][4])
{
    extern __shared__ __half smh[];
    __half* As0 = smh;
    __half* Bs0 = smh + 2 * 128 * HPAD;

    const int t = threadIdx.x, lane = t & 31, wid = t >> 5;
    const int wm = wid >> 1, wn = wid & 1;
    const int g = lane >> 2, t4 = lane & 3;

    {
#pragma unroll
        for (int i = 0; i < 4; i++) {
            int e = t + i * 256;
            int r = e >> 3, seg = e & 7;
            cp16(&As0[r * HPAD + seg * 8], A + (size_t)(m0 + r) * lda + seg * 8);
        }
#pragma unroll
        for (int i = 0; i < 2; i++) {
            int e = t + i * 256;
            int r = e >> 3, seg = e & 7;
            cp16(&Bs0[r * HPAD + seg * 8], Bt + (size_t)(n0 + r) * ldb + seg * 8);
        }
        CPASYNC_COMMIT();
    }

    const int nk = Kdim / 64;
    for (int kt = 0; kt < nk; kt++) {
        const int buf = kt & 1;
        __syncthreads();
        if (kt + 1 < nk) {
            const int k0n = (kt + 1) * 64;
            __half* Ad = As0 + (buf ^ 1) * 128 * HPAD;
            __half* Bd = Bs0 + (buf ^ 1) * 64 * HPAD;
#pragma unroll
            for (int i = 0; i < 4; i++) {
                int e = t + i * 256;
                int r = e >> 3, seg = e & 7;
                cp16(&Ad[r * HPAD + seg * 8], A + (size_t)(m0 + r) * lda + k0n + seg * 8);
            }
#pragma unroll
            for (int i = 0; i < 2; i++) {
                int e = t + i * 256;
                int r = e >> 3, seg = e & 7;
                cp16(&Bd[r * HPAD + seg * 8], Bt + (size_t)(n0 + r) * ldb + k0n + seg * 8);
            }
            CPASYNC_COMMIT();
            CPASYNC_WAIT1();
        } else {
            CPASYNC_WAIT0();
        }
        __syncthreads();

        const __half* As = As0 + buf * 128 * HPAD;
        const __half* Bs = Bs0 + buf * 64 * HPAD;
#pragma unroll
        for (int ks = 0; ks < 4; ks++) {
            uint32_t Af[2][4];
#pragma unroll
            for (int rg = 0; rg < 2; rg++) {
                int rr = wm * 32 + rg * 16;
                uint2 lo = *(const uint2*)&As[(rr + g) * HPAD + ks * 16 + t4 * 4];
                uint2 hi = *(const uint2*)&As[(rr + 8 + g) * HPAD + ks * 16 + t4 * 4];
                Af[rg][0] = lo.x; Af[rg][1] = hi.x; Af[rg][2] = lo.y; Af[rg][3] = hi.y;
            }
#pragma unroll
            for (int j = 0; j < 4; j++) {
                uint2 b = *(const uint2*)&Bs[(wn * 32 + j * 8 + g) * HPAD + ks * 16 + t4 * 4];
                mma_f16(acc[0][j], Af[0], b.x, b.y);
                mma_f16(acc[1][j], Af[1], b.x, b.y);
            }
        }
    }
}

__global__ __launch_bounds__(256, 3) void qkv_projh_kernel(
    const __half* __restrict__ xh,
    const __half* __restrict__ Wtq, const float* __restrict__ bq,
    const __half* __restrict__ Wtk, const float* __restrict__ bk,
    const __half* __restrict__ Wtv, const float* __restrict__ bv,
    __half* __restrict__ Qo, __half* __restrict__ Ko, __half* __restrict__ Vo)
{
    const int seg = blockIdx.x;
    const int m0 = blockIdx.y * 128;
    const __half* Bt; const float* bias; __half* C;
    int ldc, n0; float bscale = 1.f;
    if (seg < 8)       { Bt = Wtq; bias = bq; C = Qo; ldc = DQ;  n0 = seg * 64; bscale = QSCALE; }
    else if (seg < 10) { Bt = Wtk; bias = bk; C = Ko; ldc = DKV; n0 = (seg - 8) * 64; }
    else               { Bt = Wtv; bias = bv; C = Vo; ldc = DKV; n0 = (seg - 10) * 64; }

    float acc[2][4][4];
#pragma unroll
    for (int i = 0; i < 2; i++)
#pragma unroll
        for (int j = 0; j < 4; j++)
#pragma unroll
            for (int c = 0; c < 4; c++) acc[i][j][c] = 0.f;

    projh_loop(xh, DIMX, Bt, DIMX, DIMX, m0, n0, acc);

    const int lane = threadIdx.x & 31, wid = threadIdx.x >> 5;
    const int wm = wid >> 1, wn = wid & 1, g = lane >> 2, t4 = lane & 3;
#pragma unroll
    for (int rg = 0; rg < 2; rg++) {
        int r0 = m0 + wm * 32 + rg * 16 + g;
#pragma unroll
        for (int j = 0; j < 4; j++) {
            int c = n0 + wn * 32 + j * 8 + t4 * 2;
            float b0 = bias[c] * bscale, b1 = bias[c + 1] * bscale;
            int pos = ipos(c);
            *(uint32_t*)(C + (size_t)r0 * ldc + pos) =
                pack2(acc[rg][j][0] + b0, acc[rg][j][1] + b1);
            *(uint32_t*)(C + (size_t)(r0 + 8) * ldc + pos) =
                pack2(acc[rg][j][2] + b0, acc[rg][j][3] + b1);
        }
    }
}

__global__ __launch_bounds__(256, 3) void out_projh_kernel(
    const __half* __restrict__ Ch, const __half* __restrict__ Wto,
    const float* __restrict__ bo, float* __restrict__ out)
{
    const int n0 = blockIdx.x * 64;
    const int m0 = blockIdx.y * 128;

    float acc[2][4][4];
#pragma unroll
    for (int i = 0; i < 2; i++)
#pragma unroll
        for (int j = 0; j < 4; j++)
#pragma unroll
            for (int c = 0; c < 4; c++) acc[i][j][c] = 0.f;

    projh_loop(Ch, DQ, Wto, DQ, DQ, m0, n0, acc);

    const int lane = threadIdx.x & 31, wid = threadIdx.x >> 5;
    const int wm = wid >> 1, wn = wid & 1, g = lane >> 2, t4 = lane & 3;
#pragma unroll
    for (int rg = 0; rg < 2; rg++) {
        int r0 = m0 + wm * 32 + rg * 16 + g;
#pragma unroll
        for (int j = 0; j < 4; j++) {
            int col = n0 + wn * 32 + j * 8 + t4 * 2;
            float b0 = bo[col], b1 = bo[col + 1];
            *(float2*)(out + (size_t)r0 * DIMX + col) =
                make_float2(acc[rg][j][0] + b0, acc[rg][j][1] + b1);
            *(float2*)(out + (size_t)(r0 + 8) * DIMX + col) =
                make_float2(acc[rg][j][2] + b0, acc[rg][j][3] + b1);
        }
    }
}

// ===========================================================================
// Pass 1: partial rowsums. 128 thr, 4 warps x 32 rows = 128-row tile.
// grid (SEQ/128, HQ, RSPLIT). 64-key tiles, cp.async, B-frag reuse x2.
// ===========================================================================
__global__ __launch_bounds__(128, 8) void rowsum_kernel(
    const __half* __restrict__ Qh, const __half* __restrict__ Kh,
    float* __restrict__ rspart)
{
    __shared__ __half Ks[2][64 * HPAD];

    const int t = threadIdx.x, lane = t & 31, wid = t >> 5;
    const int g = lane >> 2, t4 = lane & 3;
    const int m0 = blockIdx.x * 128, h = blockIdx.y, sp = blockIdx.z;
    const int kh = h / NREP;

    uint32_t qfA[4][4], qfB[4][4];
    load_qfrag(qfA, Qh, m0 + wid * 32, h, g, t4);
    load_qfrag(qfB, Qh, m0 + wid * 32 + 16, h, g, t4);

    float rs[4] = {0.f, 0.f, 0.f, 0.f};
    const int it0 = sp * (SEQ / 64 / RSPLIT);
    const int it1 = it0 + (SEQ / 64 / RSPLIT);

    {
        const int n0 = it0 * 64;
#pragma unroll
        for (int i = 0; i < 4; i++) {
            int e = t + i * 128;
            int r = e >> 3, seg = e & 7;
            cp16(&Ks[0][r * HPAD + seg * 8],
                 Kh + (size_t)(n0 + r) * DKV + kh * HD + seg * 8);
        }
        CPASYNC_COMMIT();
    }

    for (int it = it0; it < it1; it++) {
        const int buf = (it - it0) & 1;
        __syncthreads();
        if (it + 1 < it1) {
            const int n0 = (it + 1) * 64;
#pragma unroll
            for (int i = 0; i < 4; i++) {
                int e = t + i * 128;
                int r = e >> 3, seg = e & 7;
                cp16(&Ks[buf ^ 1][r * HPAD + seg * 8],
                     Kh + (size_t)(n0 + r) * DKV + kh * HD + seg * 8);
            }
            CPASYNC_COMMIT();
            CPASYNC_WAIT1();
        } else {
            CPASYNC_WAIT0();
        }
        __syncthreads();

        const __half* kb = Ks[buf];
#pragma unroll
        for (int j = 0; j < 8; j++) {
            float sA[4] = {0.f, 0.f, 0.f, 0.f};
            float sB[4] = {0.f, 0.f, 0.f, 0.f};
#pragma unroll
            for (int ks = 0; ks < 4; ks++) {
                uint2 b = bfrag(kb, j * 8 + g, ks, t4);
                mma_f16(sA, qfA[ks], b.x, b.y);
                mma_f16(sB, qfB[ks], b.x, b.y);
            }
            float2 e0 = ex2h2(sA[0], sA[1]);
            float2 e1 = ex2h2(sA[2], sA[3]);
            float2 e2 = ex2h2(sB[0], sB[1]);
            float2 e3 = ex2h2(sB[2], sB[3]);
            rs[0] += e0.x + e0.y;
            rs[1] += e1.x + e1.y;
            rs[2] += e2.x + e2.y;
            rs[3] += e3.x + e3.y;
        }
    }

#pragma unroll
    for (int i = 0; i < 4; i++) {
        rs[i] += __shfl_xor_sync(0xffffffffu, rs[i], 1);
        rs[i] += __shfl_xor_sync(0xffffffffu, rs[i], 2);
    }
    if (t4 == 0) {
        float* dst = rspart + (size_t)sp * HQ * SEQ + (size_t)h * SEQ + m0 + wid * 32;
        dst[g]      = rs[0];
        dst[g + 8]  = rs[1];
        dst[g + 16] = rs[2];
        dst[g + 24] = rs[3];
    }
}

// ===========================================================================
// Pass 2: fused scores + softmax write (.cs) + PV. 128 thr, 4 warps x 16 rows.
// grid (SEQ/64, HQ). cp.async double buffer. ctx stored half interleaved.
// ===========================================================================
__global__ __launch_bounds__(128) void fused_att_kernel(
    const __half* __restrict__ Qh, const __half* __restrict__ Kh,
    const __half* __restrict__ Vt, const float* __restrict__ rspart,
    float* __restrict__ att, __half* __restrict__ Ch)
{
    __shared__ __half Ks[2][64 * HPAD];
    __shared__ __half Vs[2][64 * HPAD];
    __shared__ float sinv[64];

    const int t = threadIdx.x, lane = t & 31, wid = t >> 5;
    const int g = lane >> 2, t4 = lane & 3;
    const int m0 = blockIdx.x * 64, h = blockIdx.y;
    const int kh = h / NREP;

    if (t < 64) {
        const float* rp = rspart + (size_t)h * SEQ + m0 + t;
        float s = rp[0];
#pragma unroll
        for (int i = 1; i < RSPLIT; i++) s += rp[(size_t)i * HQ * SEQ];
        sinv[t] = 1.0f / s;
    }

    uint32_t qf[4][4];
    load_qfrag(qf, Qh, m0 + wid * 16, h, g, t4);

    const __half* vth = Vt + (size_t)kh * HD * SEQ;

    {
#pragma unroll
        for (int i = 0; i < 4; i++) {
            int e = t + i * 128;
            int r = e >> 3, seg = e & 7;
            cp16(&Ks[0][r * HPAD + seg * 8],
                 Kh + (size_t)r * DKV + kh * HD + seg * 8);
            cp16(&Vs[0][r * HPAD + seg * 8],
                 vth + (size_t)r * SEQ + seg * 8);
        }
        CPASYNC_COMMIT();
    }
    __syncthreads();   // sinv visible

    const int rl = wid * 16 + g;
    const float inv_lo = sinv[rl];
    const float inv_hi = sinv[rl + 8];

    float ctx[8][4];
#pragma unroll
    for (int j = 0; j < 8; j++)
#pragma unroll
        for (int c = 0; c < 4; c++) ctx[j][c] = 0.f;

    float* atth = att + (size_t)h * SEQ * SEQ;

    for (int it = 0; it < SEQ / 64; it++) {
        const int buf = it & 1;
        __syncthreads();
        if (it + 1 < SEQ / 64) {
            const int k0n = (it + 1) * 64;
#pragma unroll
            for (int i = 0; i < 4; i++) {
                int e = t + i * 128;
                int r = e >> 3, seg = e & 7;
                cp16(&Ks[buf ^ 1][r * HPAD + seg * 8],
                     Kh + (size_t)(k0n + r) * DKV + kh * HD + seg * 8);
                cp16(&Vs[buf ^ 1][r * HPAD + seg * 8],
                     vth + (size_t)r * SEQ + k0n + seg * 8);
            }
            CPASYNC_COMMIT();
            CPASYNC_WAIT1();
        } else {
            CPASYNC_WAIT0();
        }
        __syncthreads();

        const __half* kb = Ks[buf];
        const __half* vb = Vs[buf];
        const int k0 = it * 64;

        float sacc[8][4];
#pragma unroll
        for (int j = 0; j < 8; j++)
#pragma unroll
            for (int c = 0; c < 4; c++) sacc[j][c] = 0.f;

#pragma unroll
        for (int ks = 0; ks < 4; ks++) {
#pragma unroll
            for (int j = 0; j < 8; j++) {
                uint2 b = bfrag(kb, j * 8 + g, ks, t4);
                mma_f16(sacc[j], qf[ks], b.x, b.y);
            }
        }

        const size_t rowbase = (size_t)(m0 + rl) * SEQ + k0;
        uint32_t pk[8][2];
#pragma unroll
        for (int j = 0; j < 8; j++) {
            float p0 = ex2(sacc[j][0]) * inv_lo;
            float p1 = ex2(sacc[j][1]) * inv_lo;
            float p2 = ex2(sacc[j][2]) * inv_hi;
            float p3 = ex2(sacc[j][3]) * inv_hi;
            int cj = j * 8 + t4 * 2;
            stg_cs_v2(atth + rowbase + cj, p0, p1);
            stg_cs_v2(atth + rowbase + 8 * SEQ + cj, p2, p3);
            pk[j][0] = pack2(p0, p1);
            pk[j][1] = pack2(p2, p3);
        }

#pragma unroll
        for (int kc = 0; kc < 4; kc++) {
            uint32_t A[4] = { pk[2 * kc][0], pk[2 * kc][1],
                              pk[2 * kc + 1][0], pk[2 * kc + 1][1] };
#pragma unroll
            for (int jj = 0; jj < 8; jj++) {
                uint2 b = bfrag(vb, jj * 8 + g, kc, t4);
                mma_f16(ctx[jj], A, b.x, b.y);
            }
        }
    }

    // store context (half, pair-interleaved)
#pragma unroll
    for (int jj = 0; jj < 8; jj++) {
        int c = h * HD + jj * 8 + t4 * 2;
        int pos = ipos(c);
        *(uint32_t*)(Ch + (size_t)(m0 + rl) * DQ + pos) = pack2(ctx[jj][0], ctx[jj][1]);
        *(uint32_t*)(Ch + (size_t)(m0 + rl + 8) * DQ + pos) = pack2(ctx[jj][2], ctx[jj][3]);
    }
}

// ===========================================================================
extern "C" void kernel_launch(void* const* d_in, const int* in_sizes, int n_in,
                              void* d_out, int out_size)
{
    const float* x  = (const float*)d_in[0];
    const float* Wq = (const float*)d_in[1];
    const float* bq = (const float*)d_in[2];
    const float* Wk = (const float*)d_in[3];
    const float* bk = (const float*)d_in[4];
    const float* Wv = (const float*)d_in[5];
    const float* bv = (const float*)d_in[6];
    const float* Wo = (const float*)d_in[7];
    const float* bo = (const float*)d_in[8];

    float* out = (float*)d_out;                 // [4096, 768]
    float* att = out + (size_t)SEQ * DIMX;      // [8, 4096, 4096]

    void* p;
    cudaGetSymbolAddress(&p, g_xh);     __half* xhp  = (__half*)p;
    cudaGetSymbolAddress(&p, g_Wtq);    __half* Wtqp = (__half*)p;
    cudaGetSymbolAddress(&p, g_Wtk);    __half* Wtkp = (__half*)p;
    cudaGetSymbolAddress(&p, g_Wtv);    __half* Wtvp = (__half*)p;
    cudaGetSymbolAddress(&p, g_Wto);    __half* Wtop = (__half*)p;
    cudaGetSymbolAddress(&p, g_Qh);     __half* Qhp  = (__half*)p;
    cudaGetSymbolAddress(&p, g_Kh);     __half* Khp  = (__half*)p;
    cudaGetSymbolAddress(&p, g_Vh);     __half* Vhp  = (__half*)p;
    cudaGetSymbolAddress(&p, g_Vt);     __half* Vtp  = (__half*)p;
    cudaGetSymbolAddress(&p, g_Ch);     __half* Chp  = (__half*)p;
    cudaGetSymbolAddress(&p, g_rspart); float*  Rpp  = (float*)p;

    cudaFuncSetAttribute(qkv_projh_kernel,
        cudaFuncAttributeMaxDynamicSharedMemorySize, PROJH_SMEM);
    cudaFuncSetAttribute(out_projh_kernel,
        cudaFuncAttributeMaxDynamicSharedMemorySize, PROJH_SMEM);

    // preps: x -> half (interleaved); ALL weight transposes in one launch.
    // Grid z=4 weights; x covers K<=768, y covers N<=768 (early-out inside).
    f2h_kernel<<<(SEQ * DIMX) / 1024, 256>>>(x, xhp);
    wt4_kernel<<<dim3(DIMX / 32, DIMX / 32, 4), dim3(32, 8)>>>(
        Wq, Wk, Wv, Wo, Wtqp, Wtkp, Wtvp, Wtop);

    // QKV projections (fp16 mma)
    qkv_projh_kernel<<<dim3(12, SEQ / 128), 256, PROJH_SMEM>>>(
        xhp, Wtqp, bq, Wtkp, bk, Wtvp, bv, Qhp, Khp, Vhp);

    // V transpose
    vt_kernel<<<dim3(SEQ / 32, HD / 32, HKV), dim3(32, 8)>>>(Vhp, Vtp);

    // Pass 1: partial rowsums (8-way key split)
    rowsum_kernel<<<dim3(SEQ / 128, HQ, RSPLIT), 128>>>(Qhp, Khp, Rpp);

    // Pass 2: fused scores + softmax write + PV
    fused_att_kernel<<<dim3(SEQ / 64, HQ), 128>>>(Qhp, Khp, Vtp, Rpp, att, Chp);

    // out = ctx @ Wo + bo (fp16 mma)
    out_projh_kernel<<<dim3(DIMX / 64, SEQ / 128), 256, PROJH_SMEM>>>(
        Chp, Wtop, bo, out);
}

// round 17
// speedup vs baseline: 1.3619x; 1.0611x over previous
#include <cuda_runtime.h>
#include <cuda_fp16.h>
#include <cstdint>

// Problem constants
#define DIMX 768
#define HQ   8
#define HKV  2
#define HD   64
#define SEQ  4096
#define NREP (HQ / HKV)   // 4
#define RSPLIT 8          // rowsum key split
#define FSPLIT 2          // fused key split
#define DQ   (HQ * HD)    // 512
#define DKV  (HKV * HD)   // 128

// Scratch (allocation-free rule: __device__ globals) — all half, pair-interleaved
__device__ __half g_xh[SEQ * DIMX];
__device__ __half g_Wtq[DQ * DIMX];
__device__ __half g_Wtk[DKV * DIMX];
__device__ __half g_Wtv[DKV * DIMX];
__device__ __half g_Wto[DIMX * DQ];
__device__ __half g_Qh[SEQ * DQ];
__device__ __half g_Kh[SEQ * DKV];
__device__ __half g_Vh[SEQ * DKV];
__device__ __half g_Vt[HKV * HD * SEQ];
__device__ __half g_Cp[FSPLIT * SEQ * DQ];   // ctx partials
__device__ __half g_Ch[SEQ * DQ];            // summed context
__device__ float  g_rspart[RSPLIT * HQ * SEQ];

// ===========================================================================
// helpers
// ===========================================================================
__device__ __forceinline__ void mma_f16(float* c, const uint32_t* a, uint32_t b0, uint32_t b1) {
    asm volatile(
        "mma.sync.aligned.m16n8k16.row.col.f32.f16.f16.f32 "
        "{%0,%1,%2,%3}, {%4,%5,%6,%7}, {%8,%9}, {%0,%1,%2,%3};"
        : "+f"(c[0]), "+f"(c[1]), "+f"(c[2]), "+f"(c[3])
        : "r"(a[0]), "r"(a[1]), "r"(a[2]), "r"(a[3]), "r"(b0), "r"(b1));
}
__device__ __forceinline__ uint32_t pack2(float a, float b) {
    __half2 h = __floats2half2_rn(a, b);
    return *reinterpret_cast<uint32_t*>(&h);
}
__device__ __forceinline__ float ex2(float x) {
    float y;
    asm("ex2.approx.f32 %0, %1;" : "=f"(y) : "f"(x));
    return y;
}
__device__ __forceinline__ float2 ex2h2(float a, float b) {
    uint32_t in = pack2(a, b);
    uint32_t out;
    asm("ex2.approx.f16x2 %0, %1;" : "=r"(out) : "r"(in));
    __half2 h = *reinterpret_cast<__half2*>(&out);
    return __half22float2(h);
}
__device__ __forceinline__ void stg_cs_v2(float* p, float a, float b) {
    asm volatile("st.global.cs.v2.f32 [%0], {%1, %2};"
                 :: "l"(p), "f"(a), "f"(b) : "memory");
}
// cp.async helpers
__device__ __forceinline__ void cp16(__half* sdst, const __half* gsrc) {
    uint32_t s;
    asm("{ .reg .u64 a; cvta.to.shared.u64 a, %1; cvt.u32.u64 %0, a; }"
        : "=r"(s) : "l"(sdst));
    asm volatile("cp.async.cg.shared.global [%0], [%1], 16;"
                 :: "r"(s), "l"(gsrc) : "memory");
}
#define CPASYNC_COMMIT() asm volatile("cp.async.commit_group;" ::: "memory")
#define CPASYNC_WAIT1()  asm volatile("cp.async.wait_group 1;" ::: "memory")
#define CPASYNC_WAIT0()  asm volatile("cp.async.wait_group 0;" ::: "memory")

// pair-interleave maps (within 16-element groups)
__device__ __forceinline__ int perm16(int s) {
    int q = s & 15;
    int p = (q < 8) ? ((q >> 1) * 4 + (q & 1))
                    : (((q - 8) >> 1) * 4 + 2 + (q & 1));
    return (s & ~15) | p;
}
__device__ __forceinline__ int ipos(int c) {
    int off = c & 15;
    int stored = (off < 8) ? (2 * off) : (2 * (off - 8) + 2);
    return (c & ~15) | stored;
}

#define QSCALE 0.1803368801111204f   // 1/sqrt(64) * log2(e)
#define HPAD 80                      // half tile row stride

// ===========================================================================
// Prep: fp32 -> half, pair-interleaved (flat)
// ===========================================================================
__global__ void f2h_kernel(const float* __restrict__ src, __half* __restrict__ dst)
{
    int i = blockIdx.x * 256 + threadIdx.x;
    int u = i & 3;
    int chunk = i >> 2;
    const float* s = src + (size_t)chunk * 16 + 2 * u;
    float2 lo = *(const float2*)s;
    float2 hi = *(const float2*)(s + 8);
    uint2 o;
    o.x = pack2(lo.x, lo.y);
    o.y = pack2(hi.x, hi.y);
    *(uint2*)((char*)dst + (size_t)i * 8) = o;
}

// ===========================================================================
// Prep: ALL FOUR weight transposes in one kernel. Grid (24, 24, 4).
// ===========================================================================
__global__ void wt4_kernel(
    const float* __restrict__ Wq, const float* __restrict__ Wk,
    const float* __restrict__ Wv, const float* __restrict__ Wo,
    __half* __restrict__ Wtq, __half* __restrict__ Wtk,
    __half* __restrict__ Wtv, __half* __restrict__ Wto)
{
    __shared__ float tile[32][33];
    const int which = blockIdx.z;
    const float* W;
    __half* Wt;
    int K, N;
    float scale = 1.f;
    if (which == 0)      { W = Wq; Wt = Wtq; K = DIMX; N = DQ;  scale = QSCALE; }
    else if (which == 1) { W = Wk; Wt = Wtk; K = DIMX; N = DKV; }
    else if (which == 2) { W = Wv; Wt = Wtv; K = DIMX; N = DKV; }
    else                 { W = Wo; Wt = Wto; K = DQ;   N = DIMX; }

    const int k0 = blockIdx.x * 32, n0 = blockIdx.y * 32;
    if (k0 >= K || n0 >= N) return;
    const int tx = threadIdx.x, ty = threadIdx.y;
#pragma unroll
    for (int i = 0; i < 32; i += 8)
        tile[ty + i][tx] = W[(size_t)(k0 + ty + i) * N + n0 + tx];
    __syncthreads();
#pragma unroll
    for (int i = 0; i < 32; i += 8)
        Wt[(size_t)(n0 + ty + i) * K + (k0 & ~31) + perm16(k0 % 32 + tx)] =
            __float2half_rn(tile[tx][ty + i] * scale);
}

// ===========================================================================
// Prep: Vh -> Vt [kh][d][s] (interleaved s)
// ===========================================================================
__global__ void vt_kernel(const __half* __restrict__ Vh, __half* __restrict__ Vt)
{
    __shared__ __half tile[32][33];
    const int kh = blockIdx.z;
    const int s0 = blockIdx.x * 32;
    const int d0 = blockIdx.y * 32;
    const int tx = threadIdx.x, ty = threadIdx.y;
#pragma unroll
    for (int i = 0; i < 32; i += 8)
        tile[ty + i][tx] = Vh[(size_t)(s0 + ty + i) * DKV + kh * HD + perm16(d0 + tx)];
    __syncthreads();
#pragma unroll
    for (int i = 0; i < 32; i += 8)
        Vt[(size_t)kh * HD * SEQ + (size_t)(d0 + ty + i) * SEQ + s0 + perm16(tx)] =
            tile[tx][ty + i];
}

// ===========================================================================
// ctx partial sum: Ch = Cp[0] + Cp[1]  (vectorized half2 x4)
// ===========================================================================
__global__ void addc_kernel(const __half* __restrict__ Cp, __half* __restrict__ Ch)
{
    int i = blockIdx.x * 256 + threadIdx.x;   // uint4 index (8 halves)
    const __half2* a = (const __half2*)(Cp + (size_t)i * 8);
    const __half2* b = (const __half2*)(Cp + (size_t)SEQ * DQ + (size_t)i * 8);
    __half2* o = (__half2*)(Ch + (size_t)i * 8);
#pragma unroll
    for (int k = 0; k < 4; k++) o[k] = __hadd2(a[k], b[k]);
}

// ===========================================================================
// Q fragment loader (LDG.64 from interleaved half Q)
// ===========================================================================
__device__ __forceinline__ void load_qfrag(
    uint32_t qf[4][4], const __half* __restrict__ Qh,
    int row0, int h, int g, int t4)
{
    const __half* q0 = Qh + (size_t)(row0 + g) * DQ + h * HD;
    const __half* q1 = q0 + (size_t)8 * DQ;
#pragma unroll
    for (int ks = 0; ks < 4; ks++) {
        uint2 lo = *(const uint2*)(q0 + ks * 16 + t4 * 4);
        uint2 hi = *(const uint2*)(q1 + ks * 16 + t4 * 4);
        qf[ks][0] = lo.x; qf[ks][1] = hi.x; qf[ks][2] = lo.y; qf[ks][3] = hi.y;
    }
}

__device__ __forceinline__ uint2 bfrag(const __half* base, int n, int ks, int t4) {
    return *(const uint2*)(base + n * HPAD + ks * 16 + t4 * 4);
}

// ===========================================================================
// fp16 projection mainloop (cp.async pipeline)
// ===========================================================================
#define PROJH_SMEM ((2 * 128 * HPAD + 2 * 64 * HPAD) * 2)

__device__ __forceinline__ void projh_loop(
    const __half* __restrict__ A, int lda,
    const __half* __restrict__ Bt, int ldb, int Kdim,
    int m0, int n0, float acc[2][4][4])
{
    extern __shared__ __half smh[];
    __half* As0 = smh;
    __half* Bs0 = smh + 2 * 128 * HPAD;

    const int t = threadIdx.x, lane = t & 31, wid = t >> 5;
    const int wm = wid >> 1, wn = wid & 1;
    const int g = lane >> 2, t4 = lane & 3;

    {
#pragma unroll
        for (int i = 0; i < 4; i++) {
            int e = t + i * 256;
            int r = e >> 3, seg = e & 7;
            cp16(&As0[r * HPAD + seg * 8], A + (size_t)(m0 + r) * lda + seg * 8);
        }
#pragma unroll
        for (int i = 0; i < 2; i++) {
            int e = t + i * 256;
            int r = e >> 3, seg = e & 7;
            cp16(&Bs0[r * HPAD + seg * 8], Bt + (size_t)(n0 + r) * ldb + seg * 8);
        }
        CPASYNC_COMMIT();
    }

    const int nk = Kdim / 64;
    for (int kt = 0; kt < nk; kt++) {
        const int buf = kt & 1;
        __syncthreads();
        if (kt + 1 < nk) {
            const int k0n = (kt + 1) * 64;
            __half* Ad = As0 + (buf ^ 1) * 128 * HPAD;
            __half* Bd = Bs0 + (buf ^ 1) * 64 * HPAD;
#pragma unroll
            for (int i = 0; i < 4; i++) {
                int e = t + i * 256;
                int r = e >> 3, seg = e & 7;
                cp16(&Ad[r * HPAD + seg * 8], A + (size_t)(m0 + r) * lda + k0n + seg * 8);
            }
#pragma unroll
            for (int i = 0; i < 2; i++) {
                int e = t + i * 256;
                int r = e >> 3, seg = e & 7;
                cp16(&Bd[r * HPAD + seg * 8], Bt + (size_t)(n0 + r) * ldb + k0n + seg * 8);
            }
            CPASYNC_COMMIT();
            CPASYNC_WAIT1();
        } else {
            CPASYNC_WAIT0();
        }
        __syncthreads();

        const __half* As = As0 + buf * 128 * HPAD;
        const __half* Bs = Bs0 + buf * 64 * HPAD;
#pragma unroll
        for (int ks = 0; ks < 4; ks++) {
            uint32_t Af[2][4];
#pragma unroll
            for (int rg = 0; rg < 2; rg++) {
                int rr = wm * 32 + rg * 16;
                uint2 lo = *(const uint2*)&As[(rr + g) * HPAD + ks * 16 + t4 * 4];
                uint2 hi = *(const uint2*)&As[(rr + 8 + g) * HPAD + ks * 16 + t4 * 4];
                Af[rg][0] = lo.x; Af[rg][1] = hi.x; Af[rg][2] = lo.y; Af[rg][3] = hi.y;
            }
#pragma unroll
            for (int j = 0; j < 4; j++) {
                uint2 b = *(const uint2*)&Bs[(wn * 32 + j * 8 + g) * HPAD + ks * 16 + t4 * 4];
                mma_f16(acc[0][j], Af[0], b.x, b.y);
                mma_f16(acc[1][j], Af[1], b.x, b.y);
            }
        }
    }
}

__global__ __launch_bounds__(256, 3) void qkv_projh_kernel(
    const __half* __restrict__ xh,
    const __half* __restrict__ Wtq, const float* __restrict__ bq,
    const __half* __restrict__ Wtk, const float* __restrict__ bk,
    const __half* __restrict__ Wtv, const float* __restrict__ bv,
    __half* __restrict__ Qo, __half* __restrict__ Ko, __half* __restrict__ Vo)
{
    const int seg = blockIdx.x;
    const int m0 = blockIdx.y * 128;
    const __half* Bt; const float* bias; __half* C;
    int ldc, n0; float bscale = 1.f;
    if (seg < 8)       { Bt = Wtq; bias = bq; C = Qo; ldc = DQ;  n0 = seg * 64; bscale = QSCALE; }
    else if (seg < 10) { Bt = Wtk; bias = bk; C = Ko; ldc = DKV; n0 = (seg - 8) * 64; }
    else               { Bt = Wtv; bias = bv; C = Vo; ldc = DKV; n0 = (seg - 10) * 64; }

    float acc[2][4][4];
#pragma unroll
    for (int i = 0; i < 2; i++)
#pragma unroll
        for (int j = 0; j < 4; j++)
#pragma unroll
            for (int c = 0; c < 4; c++) acc[i][j][c] = 0.f;

    projh_loop(xh, DIMX, Bt, DIMX, DIMX, m0, n0, acc);

    const int lane = threadIdx.x & 31, wid = threadIdx.x >> 5;
    const int wm = wid >> 1, wn = wid & 1, g = lane >> 2, t4 = lane & 3;
#pragma unroll
    for (int rg = 0; rg < 2; rg++) {
        int r0 = m0 + wm * 32 + rg * 16 + g;
#pragma unroll
        for (int j = 0; j < 4; j++) {
            int c = n0 + wn * 32 + j * 8 + t4 * 2;
            float b0 = bias[c] * bscale, b1 = bias[c + 1] * bscale;
            int pos = ipos(c);
            *(uint32_t*)(C + (size_t)r0 * ldc + pos) =
                pack2(acc[rg][j][0] + b0, acc[rg][j][1] + b1);
            *(uint32_t*)(C + (size_t)(r0 + 8) * ldc + pos) =
                pack2(acc[rg][j][2] + b0, acc[rg][j][3] + b1);
        }
    }
}

__global__ __launch_bounds__(256, 3) void out_projh_kernel(
    const __half* __restrict__ Ch, const __half* __restrict__ Wto,
    const float* __restrict__ bo, float* __restrict__ out)
{
    const int n0 = blockIdx.x * 64;
    const int m0 = blockIdx.y * 128;

    float acc[2][4][4];
#pragma unroll
    for (int i = 0; i < 2; i++)
#pragma unroll
        for (int j = 0; j < 4; j++)
#pragma unroll
            for (int c = 0; c < 4; c++) acc[i][j][c] = 0.f;

    projh_loop(Ch, DQ, Wto, DQ, DQ, m0, n0, acc);

    const int lane = threadIdx.x & 31, wid = threadIdx.x >> 5;
    const int wm = wid >> 1, wn = wid & 1, g = lane >> 2, t4 = lane & 3;
#pragma unroll
    for (int rg = 0; rg < 2; rg++) {
        int r0 = m0 + wm * 32 + rg * 16 + g;
#pragma unroll
        for (int j = 0; j < 4; j++) {
            int col = n0 + wn * 32 + j * 8 + t4 * 2;
            float b0 = bo[col], b1 = bo[col + 1];
            *(float2*)(out + (size_t)r0 * DIMX + col) =
                make_float2(acc[rg][j][0] + b0, acc[rg][j][1] + b1);
            *(float2*)(out + (size_t)(r0 + 8) * DIMX + col) =
                make_float2(acc[rg][j][2] + b0, acc[rg][j][3] + b1);
        }
    }
}

// ===========================================================================
// Pass 1: partial rowsums. 128 thr, 4 warps x 32 rows = 128-row tile.
// grid (SEQ/128, HQ, RSPLIT). 64-key tiles, cp.async, B-frag reuse x2.
// ===========================================================================
__global__ __launch_bounds__(128, 8) void rowsum_kernel(
    const __half* __restrict__ Qh, const __half* __restrict__ Kh,
    float* __restrict__ rspart)
{
    __shared__ __half Ks[2][64 * HPAD];

    const int t = threadIdx.x, lane = t & 31, wid = t >> 5;
    const int g = lane >> 2, t4 = lane & 3;
    const int m0 = blockIdx.x * 128, h = blockIdx.y, sp = blockIdx.z;
    const int kh = h / NREP;

    uint32_t qfA[4][4], qfB[4][4];
    load_qfrag(qfA, Qh, m0 + wid * 32, h, g, t4);
    load_qfrag(qfB, Qh, m0 + wid * 32 + 16, h, g, t4);

    float rs[4] = {0.f, 0.f, 0.f, 0.f};
    const int it0 = sp * (SEQ / 64 / RSPLIT);
    const int it1 = it0 + (SEQ / 64 / RSPLIT);

    {
        const int n0 = it0 * 64;
#pragma unroll
        for (int i = 0; i < 4; i++) {
            int e = t + i * 128;
            int r = e >> 3, seg = e & 7;
            cp16(&Ks[0][r * HPAD + seg * 8],
                 Kh + (size_t)(n0 + r) * DKV + kh * HD + seg * 8);
        }
        CPASYNC_COMMIT();
    }

    for (int it = it0; it < it1; it++) {
        const int buf = (it - it0) & 1;
        __syncthreads();
        if (it + 1 < it1) {
            const int n0 = (it + 1) * 64;
#pragma unroll
            for (int i = 0; i < 4; i++) {
                int e = t + i * 128;
                int r = e >> 3, seg = e & 7;
                cp16(&Ks[buf ^ 1][r * HPAD + seg * 8],
                     Kh + (size_t)(n0 + r) * DKV + kh * HD + seg * 8);
            }
            CPASYNC_COMMIT();
            CPASYNC_WAIT1();
        } else {
            CPASYNC_WAIT0();
        }
        __syncthreads();

        const __half* kb = Ks[buf];
#pragma unroll
        for (int j = 0; j < 8; j++) {
            float sA[4] = {0.f, 0.f, 0.f, 0.f};
            float sB[4] = {0.f, 0.f, 0.f, 0.f};
#pragma unroll
            for (int ks = 0; ks < 4; ks++) {
                uint2 b = bfrag(kb, j * 8 + g, ks, t4);
                mma_f16(sA, qfA[ks], b.x, b.y);
                mma_f16(sB, qfB[ks], b.x, b.y);
            }
            float2 e0 = ex2h2(sA[0], sA[1]);
            float2 e1 = ex2h2(sA[2], sA[3]);
            float2 e2 = ex2h2(sB[0], sB[1]);
            float2 e3 = ex2h2(sB[2], sB[3]);
            rs[0] += e0.x + e0.y;
            rs[1] += e1.x + e1.y;
            rs[2] += e2.x + e2.y;
            rs[3] += e3.x + e3.y;
        }
    }

#pragma unroll
    for (int i = 0; i < 4; i++) {
        rs[i] += __shfl_xor_sync(0xffffffffu, rs[i], 1);
        rs[i] += __shfl_xor_sync(0xffffffffu, rs[i], 2);
    }
    if (t4 == 0) {
        float* dst = rspart + (size_t)sp * HQ * SEQ + (size_t)h * SEQ + m0 + wid * 32;
        dst[g]      = rs[0];
        dst[g + 8]  = rs[1];
        dst[g + 16] = rs[2];
        dst[g + 24] = rs[3];
    }
}

// ===========================================================================
// Pass 2: fused scores + softmax write (.cs) + PV. 128 thr, 4 warps x 16 rows.
// grid (SEQ/64, HQ, FSPLIT): each block covers keys [sp*2048, sp*2048+2048).
// ctx written to per-split partial buffers.
// ===========================================================================
__global__ __launch_bounds__(128) void fused_att_kernel(
    const __half* __restrict__ Qh, const __half* __restrict__ Kh,
    const __half* __restrict__ Vt, const float* __restrict__ rspart,
    float* __restrict__ att, __half* __restrict__ Cp)
{
    __shared__ __half Ks[2][64 * HPAD];
    __shared__ __half Vs[2][64 * HPAD];
    __shared__ float sinv[64];

    const int t = threadIdx.x, lane = t & 31, wid = t >> 5;
    const int g = lane >> 2, t4 = lane & 3;
    const int m0 = blockIdx.x * 64, h = blockIdx.y, sp = blockIdx.z;
    const int kh = h / NREP;

    if (t < 64) {
        const float* rp = rspart + (size_t)h * SEQ + m0 + t;
        float s = rp[0];
#pragma unroll
        for (int i = 1; i < RSPLIT; i++) s += rp[(size_t)i * HQ * SEQ];
        sinv[t] = 1.0f / s;
    }

    uint32_t qf[4][4];
    load_qfrag(qf, Qh, m0 + wid * 16, h, g, t4);

    const __half* vth = Vt + (size_t)kh * HD * SEQ;
    const int it0 = sp * (SEQ / 64 / FSPLIT);
    const int it1 = it0 + (SEQ / 64 / FSPLIT);

    {
        const int k00 = it0 * 64;
#pragma unroll
        for (int i = 0; i < 4; i++) {
            int e = t + i * 128;
            int r = e >> 3, seg = e & 7;
            cp16(&Ks[0][r * HPAD + seg * 8],
                 Kh + (size_t)(k00 + r) * DKV + kh * HD + seg * 8);
            cp16(&Vs[0][r * HPAD + seg * 8],
                 vth + (size_t)r * SEQ + k00 + seg * 8);
        }
        CPASYNC_COMMIT();
    }
    __syncthreads();   // sinv visible

    const int rl = wid * 16 + g;
    const float inv_lo = sinv[rl];
    const float inv_hi = sinv[rl + 8];

    float ctx[8][4];
#pragma unroll
    for (int j = 0; j < 8; j++)
#pragma unroll
        for (int c = 0; c < 4; c++) ctx[j][c] = 0.f;

    float* atth = att + (size_t)h * SEQ * SEQ;

    for (int it = it0; it < it1; it++) {
        const int buf = (it - it0) & 1;
        __syncthreads();
        if (it + 1 < it1) {
            const int k0n = (it + 1) * 64;
#pragma unroll
            for (int i = 0; i < 4; i++) {
                int e = t + i * 128;
                int r = e >> 3, seg = e & 7;
                cp16(&Ks[buf ^ 1][r * HPAD + seg * 8],
                     Kh + (size_t)(k0n + r) * DKV + kh * HD + seg * 8);
                cp16(&Vs[buf ^ 1][r * HPAD + seg * 8],
                     vth + (size_t)r * SEQ + k0n + seg * 8);
            }
            CPASYNC_COMMIT();
            CPASYNC_WAIT1();
        } else {
            CPASYNC_WAIT0();
        }
        __syncthreads();

        const __half* kb = Ks[buf];
        const __half* vb = Vs[buf];
        const int k0 = it * 64;

        float sacc[8][4];
#pragma unroll
        for (int j = 0; j < 8; j++)
#pragma unroll
            for (int c = 0; c < 4; c++) sacc[j][c] = 0.f;

#pragma unroll
        for (int ks = 0; ks < 4; ks++) {
#pragma unroll
            for (int j = 0; j < 8; j++) {
                uint2 b = bfrag(kb, j * 8 + g, ks, t4);
                mma_f16(sacc[j], qf[ks], b.x, b.y);
            }
        }

        const size_t rowbase = (size_t)(m0 + rl) * SEQ + k0;
        uint32_t pk[8][2];
#pragma unroll
        for (int j = 0; j < 8; j++) {
            float p0 = ex2(sacc[j][0]) * inv_lo;
            float p1 = ex2(sacc[j][1]) * inv_lo;
            float p2 = ex2(sacc[j][2]) * inv_hi;
            float p3 = ex2(sacc[j][3]) * inv_hi;
            int cj = j * 8 + t4 * 2;
            stg_cs_v2(atth + rowbase + cj, p0, p1);
            stg_cs_v2(atth + rowbase + 8 * SEQ + cj, p2, p3);
            pk[j][0] = pack2(p0, p1);
            pk[j][1] = pack2(p2, p3);
        }

#pragma unroll
        for (int kc = 0; kc < 4; kc++) {
            uint32_t A[4] = { pk[2 * kc][0], pk[2 * kc][1],
                              pk[2 * kc + 1][0], pk[2 * kc + 1][1] };
#pragma unroll
            for (int jj = 0; jj < 8; jj++) {
                uint2 b = bfrag(vb, jj * 8 + g, kc, t4);
                mma_f16(ctx[jj], A, b.x, b.y);
            }
        }
    }

    // store partial context (half, pair-interleaved)
    __half* cp = Cp + (size_t)sp * SEQ * DQ;
#pragma unroll
    for (int jj = 0; jj < 8; jj++) {
        int c = h * HD + jj * 8 + t4 * 2;
        int pos = ipos(c);
        *(uint32_t*)(cp + (size_t)(m0 + rl) * DQ + pos) = pack2(ctx[jj][0], ctx[jj][1]);
        *(uint32_t*)(cp + (size_t)(m0 + rl + 8) * DQ + pos) = pack2(ctx[jj][2], ctx[jj][3]);
    }
}

// ===========================================================================
extern "C" void kernel_launch(void* const* d_in, const int* in_sizes, int n_in,
                              void* d_out, int out_size)
{
    const float* x  = (const float*)d_in[0];
    const float* Wq = (const float*)d_in[1];
    const float* bq = (const float*)d_in[2];
    const float* Wk = (const float*)d_in[3];
    const float* bk = (const float*)d_in[4];
    const float* Wv = (const float*)d_in[5];
    const float* bv = (const float*)d_in[6];
    const float* Wo = (const float*)d_in[7];
    const float* bo = (const float*)d_in[8];

    float* out = (float*)d_out;                 // [4096, 768]
    float* att = out + (size_t)SEQ * DIMX;      // [8, 4096, 4096]

    void* p;
    cudaGetSymbolAddress(&p, g_xh);     __half* xhp  = (__half*)p;
    cudaGetSymbolAddress(&p, g_Wtq);    __half* Wtqp = (__half*)p;
    cudaGetSymbolAddress(&p, g_Wtk);    __half* Wtkp = (__half*)p;
    cudaGetSymbolAddress(&p, g_Wtv);    __half* Wtvp = (__half*)p;
    cudaGetSymbolAddress(&p, g_Wto);    __half* Wtop = (__half*)p;
    cudaGetSymbolAddress(&p, g_Qh);     __half* Qhp  = (__half*)p;
    cudaGetSymbolAddress(&p, g_Kh);     __half* Khp  = (__half*)p;
    cudaGetSymbolAddress(&p, g_Vh);     __half* Vhp  = (__half*)p;
    cudaGetSymbolAddress(&p, g_Vt);     __half* Vtp  = (__half*)p;
    cudaGetSymbolAddress(&p, g_Cp);     __half* Cpp  = (__half*)p;
    cudaGetSymbolAddress(&p, g_Ch);     __half* Chp  = (__half*)p;
    cudaGetSymbolAddress(&p, g_rspart); float*  Rpp  = (float*)p;

    cudaFuncSetAttribute(qkv_projh_kernel,
        cudaFuncAttributeMaxDynamicSharedMemorySize, PROJH_SMEM);
    cudaFuncSetAttribute(out_projh_kernel,
        cudaFuncAttributeMaxDynamicSharedMemorySize, PROJH_SMEM);

    // preps
    f2h_kernel<<<(SEQ * DIMX) / 1024, 256>>>(x, xhp);
    wt4_kernel<<<dim3(DIMX / 32, DIMX / 32, 4), dim3(32, 8)>>>(
        Wq, Wk, Wv, Wo, Wtqp, Wtkp, Wtvp, Wtop);

    // QKV projections
    qkv_projh_kernel<<<dim3(12, SEQ / 128), 256, PROJH_SMEM>>>(
        xhp, Wtqp, bq, Wtkp, bk, Wtvp, bv, Qhp, Khp, Vhp);

    // V transpose
    vt_kernel<<<dim3(SEQ / 32, HD / 32, HKV), dim3(32, 8)>>>(Vhp, Vtp);

    // Pass 1: partial rowsums
    rowsum_kernel<<<dim3(SEQ / 128, HQ, RSPLIT), 128>>>(Qhp, Khp, Rpp);

    // Pass 2: fused (2-way key split -> 1024 blocks)
    fused_att_kernel<<<dim3(SEQ / 64, HQ, FSPLIT), 128>>>(
        Qhp, Khp, Vtp, Rpp, att, Cpp);

    // sum ctx partials
    addc_kernel<<<(SEQ * DQ) / 8 / 256, 256>>>(Cpp, Chp);

    // out = ctx @ Wo + bo
    out_projh_kernel<<<dim3(DIMX / 64, SEQ / 128), 256, PROJH_SMEM>>>(
        Chp, Wtop, bo, out);
}